// round 7
// baseline (speedup 1.0000x reference)
#include <cuda_runtime.h>
#include <cuda_bf16.h>
#include <math.h>
#include <stdint.h>
#include <cstdint>

#define TGTN 2048
#define SRCN 4096
#define DIMN 512
#define NHEAD 8
#define HDIM 64
#define NVOC 32000
#define EXTV 36096
#define ZSPLIT 4

// ---------------- scratch (device globals; no allocation allowed) ----------
__device__ __nv_bfloat16 g_Qb[TGTN * DIMN];                 // 2 MB (L2-resident)
__device__ __nv_bfloat16 g_Kb[SRCN * DIMN];                 // 4 MB (L2-resident)
__device__ __nv_bfloat16 g_attnb[(size_t)TGTN * SRCN];      // 16 MB head-mean attn
__device__ float         g_Zp[ZSPLIT * NHEAD * TGTN];       // partial Z sums
__device__ float         g_w[NHEAD * TGTN];                 // 0.125/Z weights
__device__ float         g_lk[TGTN];                        // log_keep
__device__ float         g_lc[TGTN];                        // log_copy

// ---------------- helpers ---------------------------------------------------
__device__ __forceinline__ float log_sigmoid_f(float x) {
    return fminf(x, 0.0f) - log1pf(expf(-fabsf(x)));
}
__device__ __forceinline__ float warp_max(float v) {
    #pragma unroll
    for (int o = 16; o > 0; o >>= 1) v = fmaxf(v, __shfl_xor_sync(0xffffffffu, v, o));
    return v;
}
__device__ __forceinline__ float warp_sum(float v) {
    #pragma unroll
    for (int o = 16; o > 0; o >>= 1) v += __shfl_xor_sync(0xffffffffu, v, o);
    return v;
}
__device__ __forceinline__ float f2tf32(float x) {
    unsigned u;
    asm("cvt.rna.tf32.f32 %0, %1;" : "=r"(u) : "f"(x));
    return __uint_as_float(u);
}
__device__ __forceinline__ float4 tf32x4(float4 v) {
    v.x = f2tf32(v.x); v.y = f2tf32(v.y); v.z = f2tf32(v.z); v.w = f2tf32(v.w);
    return v;
}
__device__ __forceinline__ void mma_tf32(float* c, const unsigned* a, const unsigned* b) {
    asm volatile(
        "mma.sync.aligned.m16n8k8.row.col.f32.tf32.tf32.f32 "
        "{%0,%1,%2,%3},{%4,%5,%6,%7},{%8,%9},{%0,%1,%2,%3};\n"
        : "+f"(c[0]), "+f"(c[1]), "+f"(c[2]), "+f"(c[3])
        : "r"(a[0]), "r"(a[1]), "r"(a[2]), "r"(a[3]), "r"(b[0]), "r"(b[1]));
}
__device__ __forceinline__ void mma_bf16(float* c, const unsigned* a, const unsigned* b) {
    asm volatile(
        "mma.sync.aligned.m16n8k16.row.col.f32.bf16.bf16.f32 "
        "{%0,%1,%2,%3},{%4,%5,%6,%7},{%8,%9},{%0,%1,%2,%3};\n"
        : "+f"(c[0]), "+f"(c[1]), "+f"(c[2]), "+f"(c[3])
        : "r"(a[0]), "r"(a[1]), "r"(a[2]), "r"(a[3]), "r"(b[0]), "r"(b[1]));
}
__device__ __forceinline__ void ldsm_x4(unsigned& r0, unsigned& r1, unsigned& r2,
                                        unsigned& r3, uint32_t addr) {
    asm volatile("ldmatrix.sync.aligned.m8n8.x4.shared.b16 {%0,%1,%2,%3}, [%4];\n"
                 : "=r"(r0), "=r"(r1), "=r"(r2), "=r"(r3) : "r"(addr));
}

// swizzled 128x64-bf16 tile: row pitch 128B (8 x 16B chunks), chunk ^= (row&7)
__device__ __forceinline__ void load_tile(const __nv_bfloat16* __restrict__ g,
                                          char* sm, int tid) {
    #pragma unroll
    for (int it = 0; it < 4; it++) {
        int row = it * 32 + (tid >> 3);
        int c   = tid & 7;
        uint4 v = *(const uint4*)(g + (size_t)row * DIMN + c * 8);
        *(uint4*)(sm + row * 128 + ((c ^ (row & 7)) * 16)) = v;
    }
}
__device__ __forceinline__ uint32_t tile_addr(uint32_t base, int row0, int k0, int lane) {
    int r     = row0 + (lane & 15);
    int chunk = (k0 >> 3) + (lane >> 4);
    return base + r * 128 + ((chunk ^ (r & 7)) * 16);
}
// acc[4][4][4] += Q_tile(128x64) @ K_tile(128x64)^T  (warp tile 64x32)
__device__ __forceinline__ void mma_tile(float acc[4][4][4], uint32_t qb, uint32_t kb,
                                         int wm, int wn, int lane) {
    #pragma unroll
    for (int k0 = 0; k0 < HDIM; k0 += 16) {
        unsigned a[4][4], b[4][2];
        #pragma unroll
        for (int mi = 0; mi < 4; mi++)
            ldsm_x4(a[mi][0], a[mi][1], a[mi][2], a[mi][3],
                    tile_addr(qb, wm * 64 + mi * 16, k0, lane));
        #pragma unroll
        for (int nj = 0; nj < 2; nj++) {
            unsigned t0, t1, t2, t3;
            ldsm_x4(t0, t1, t2, t3, tile_addr(kb, wn * 32 + nj * 16, k0, lane));
            b[2 * nj][0]     = t0; b[2 * nj][1]     = t2;
            b[2 * nj + 1][0] = t1; b[2 * nj + 1][1] = t3;
        }
        #pragma unroll
        for (int mi = 0; mi < 4; mi++)
            #pragma unroll
            for (int ni = 0; ni < 4; ni++)
                mma_bf16(acc[mi][ni], a[mi], b[ni]);
    }
}

// ---------------- kernel 1: z / log_copy / log_keep -------------------------
__global__ void __launch_bounds__(256) z_kernel(
    const float* __restrict__ tgt, const float* __restrict__ w_lin,
    const float* __restrict__ b_lin)
{
    int row  = blockIdx.x * 8 + (threadIdx.x >> 5);
    int lane = threadIdx.x & 31;
    if (row >= TGTN) return;
    const float* tp = tgt + (size_t)row * DIMN;
    float s = 0.0f;
    #pragma unroll
    for (int i = 0; i < DIMN / 32; i++) s += tp[lane + i * 32] * w_lin[lane + i * 32];
    s = warp_sum(s);
    if (lane == 0) {
        float z = s + b_lin[0];
        g_lc[row] = log_sigmoid_f(z);
        g_lk[row] = log_sigmoid_f(-z);
    }
}

// ---------------- kernel 2: projection GEMM (tf32 mma, bf16 output) ---------
__global__ void __launch_bounds__(256, 2) proj_gemm_t(
    const float* __restrict__ A, const float* __restrict__ W,
    __nv_bfloat16* __restrict__ C)
{
    __shared__ float As[128 * 36];
    __shared__ float Ws[32 * 136];

    const int tid    = threadIdx.x;
    const int lane   = tid & 31;
    const int wid    = tid >> 5;
    const int warp_m = wid & 1;
    const int warp_n = wid >> 1;
    const int g      = lane >> 2;
    const int tg     = lane & 3;
    const int r0     = blockIdx.y * 128;
    const int c0     = blockIdx.x * 128;

    float acc[4][4][4];
    #pragma unroll
    for (int i = 0; i < 4; i++)
        #pragma unroll
        for (int j = 0; j < 4; j++)
            #pragma unroll
            for (int q = 0; q < 4; q++) acc[i][j][q] = 0.0f;

    for (int kc = 0; kc < DIMN; kc += 32) {
        __syncthreads();
        #pragma unroll
        for (int t = 0; t < 4; t++) {
            int idx = tid + t * 256;
            int r = idx >> 3, c4 = idx & 7;
            float4 v = *(const float4*)&A[(size_t)(r0 + r) * DIMN + kc + c4 * 4];
            *(float4*)&As[r * 36 + c4 * 4] = tf32x4(v);
        }
        #pragma unroll
        for (int t = 0; t < 4; t++) {
            int idx = tid + t * 256;
            int kr = idx >> 5, c4 = idx & 31;
            float4 v = *(const float4*)&W[(size_t)(kc + kr) * DIMN + c0 + c4 * 4];
            *(float4*)&Ws[kr * 136 + c4 * 4] = tf32x4(v);
        }
        __syncthreads();

        #pragma unroll
        for (int k0 = 0; k0 < 32; k0 += 8) {
            unsigned a[4][4], b[4][2];
            #pragma unroll
            for (int mi = 0; mi < 4; mi++) {
                int mb = warp_m * 64 + mi * 16;
                a[mi][0] = __float_as_uint(As[(mb + g    ) * 36 + k0 + tg    ]);
                a[mi][1] = __float_as_uint(As[(mb + g + 8) * 36 + k0 + tg    ]);
                a[mi][2] = __float_as_uint(As[(mb + g    ) * 36 + k0 + tg + 4]);
                a[mi][3] = __float_as_uint(As[(mb + g + 8) * 36 + k0 + tg + 4]);
            }
            #pragma unroll
            for (int ni = 0; ni < 4; ni++) {
                int nb = warp_n * 32 + ni * 8;
                b[ni][0] = __float_as_uint(Ws[(k0 + tg    ) * 136 + nb + g]);
                b[ni][1] = __float_as_uint(Ws[(k0 + tg + 4) * 136 + nb + g]);
            }
            #pragma unroll
            for (int mi = 0; mi < 4; mi++)
                #pragma unroll
                for (int ni = 0; ni < 4; ni++)
                    mma_tf32(acc[mi][ni], a[mi], b[ni]);
        }
    }

    #pragma unroll
    for (int mi = 0; mi < 4; mi++) {
        int r = r0 + warp_m * 64 + mi * 16 + g;
        #pragma unroll
        for (int ni = 0; ni < 4; ni++) {
            int c = c0 + warp_n * 32 + ni * 8 + tg * 2;
            *(__nv_bfloat162*)&C[(size_t)r * DIMN + c] =
                __floats2bfloat162_rn(acc[mi][ni][0], acc[mi][ni][1]);
            *(__nv_bfloat162*)&C[(size_t)(r + 8) * DIMN + c] =
                __floats2bfloat162_rn(acc[mi][ni][2], acc[mi][ni][3]);
        }
    }
}

// ---------------- kernel 3: phase A — Z_h[t] partial sums -------------------
// grid (16 t-tiles, 8 heads, ZSPLIT s-splits); block 256 (warps 2x4).
__global__ void __launch_bounds__(256) phaseA_kernel()
{
    __shared__ __align__(16) char sQ[128 * 128];
    __shared__ __align__(16) char sK[128 * 128];
    __shared__ float zrow[128];

    const int tid  = threadIdx.x;
    const int lane = tid & 31;
    const int wid  = tid >> 5;
    const int wm   = wid & 1;
    const int wn   = wid >> 1;
    const int g    = lane >> 2;
    const int tg   = lane & 3;
    const int bt   = blockIdx.x;
    const int h    = blockIdx.y;
    const int sp   = blockIdx.z;

    load_tile(g_Qb + (size_t)(bt * 128) * DIMN + h * HDIM, sQ, tid);
    if (tid < 128) zrow[tid] = 0.0f;
    const uint32_t qb = (uint32_t)__cvta_generic_to_shared(sQ);
    const uint32_t kb = (uint32_t)__cvta_generic_to_shared(sK);

    float zacc[4][2];
    #pragma unroll
    for (int mi = 0; mi < 4; mi++) { zacc[mi][0] = 0.0f; zacc[mi][1] = 0.0f; }

    for (int st = 0; st < (SRCN / ZSPLIT) / 128; st++) {
        __syncthreads();
        load_tile(g_Kb + (size_t)(sp * (SRCN / ZSPLIT) + st * 128) * DIMN + h * HDIM, sK, tid);
        __syncthreads();

        float acc[4][4][4];
        #pragma unroll
        for (int i = 0; i < 4; i++)
            #pragma unroll
            for (int j = 0; j < 4; j++)
                #pragma unroll
                for (int q = 0; q < 4; q++) acc[i][j][q] = 0.0f;
        mma_tile(acc, qb, kb, wm, wn, lane);

        #pragma unroll
        for (int mi = 0; mi < 4; mi++)
            #pragma unroll
            for (int ni = 0; ni < 4; ni++) {
                zacc[mi][0] += __expf(acc[mi][ni][0] * 0.125f) +
                               __expf(acc[mi][ni][1] * 0.125f);
                zacc[mi][1] += __expf(acc[mi][ni][2] * 0.125f) +
                               __expf(acc[mi][ni][3] * 0.125f);
            }
    }

    #pragma unroll
    for (int mi = 0; mi < 4; mi++)
        #pragma unroll
        for (int r = 0; r < 2; r++) {
            float v = zacc[mi][r];
            v += __shfl_xor_sync(0xffffffffu, v, 1);
            v += __shfl_xor_sync(0xffffffffu, v, 2);
            if (tg == 0) atomicAdd(&zrow[wm * 64 + mi * 16 + r * 8 + g], v);
        }
    __syncthreads();
    if (tid < 128)
        g_Zp[(sp * NHEAD + h) * TGTN + bt * 128 + tid] = zrow[tid];
}

// ---------------- kernel 3b: combine Z partials -> weights ------------------
__global__ void __launch_bounds__(256) combine_kernel()
{
    int i = blockIdx.x * 256 + threadIdx.x;   // over NHEAD*TGTN
    float z = g_Zp[i] + g_Zp[NHEAD * TGTN + i] +
              g_Zp[2 * NHEAD * TGTN + i] + g_Zp[3 * NHEAD * TGTN + i];
    g_w[i] = 0.125f / z;
}

// ---------------- kernel 4: phase B — attn tile write (bf16) ----------------
// grid (32 s-tiles, 16 t-tiles); block 256; loops all 8 heads, accumulating
// exp(S/8) * (1/(8 Z_h[t])) into registers, single 16MB attn write.
__global__ void __launch_bounds__(256) phaseB_kernel()
{
    __shared__ __align__(16) char sQ[128 * 128];
    __shared__ __align__(16) char sK[128 * 128];

    const int tid  = threadIdx.x;
    const int lane = tid & 31;
    const int wid  = tid >> 5;
    const int wm   = wid & 1;
    const int wn   = wid >> 1;
    const int g    = lane >> 2;
    const int tg   = lane & 3;
    const int bs   = blockIdx.x;
    const int bt   = blockIdx.y;

    const uint32_t qb = (uint32_t)__cvta_generic_to_shared(sQ);
    const uint32_t kb = (uint32_t)__cvta_generic_to_shared(sK);

    float attn[4][4][4];
    #pragma unroll
    for (int i = 0; i < 4; i++)
        #pragma unroll
        for (int j = 0; j < 4; j++)
            #pragma unroll
            for (int q = 0; q < 4; q++) attn[i][j][q] = 0.0f;

    for (int h = 0; h < NHEAD; h++) {
        __syncthreads();
        load_tile(g_Qb + (size_t)(bt * 128) * DIMN + h * HDIM, sQ, tid);
        load_tile(g_Kb + (size_t)(bs * 128) * DIMN + h * HDIM, sK, tid);
        __syncthreads();

        float acc[4][4][4];
        #pragma unroll
        for (int i = 0; i < 4; i++)
            #pragma unroll
            for (int j = 0; j < 4; j++)
                #pragma unroll
                for (int q = 0; q < 4; q++) acc[i][j][q] = 0.0f;
        mma_tile(acc, qb, kb, wm, wn, lane);

        #pragma unroll
        for (int mi = 0; mi < 4; mi++) {
            int r0 = bt * 128 + wm * 64 + mi * 16 + g;
            float w0 = g_w[h * TGTN + r0];
            float w1 = g_w[h * TGTN + r0 + 8];
            #pragma unroll
            for (int ni = 0; ni < 4; ni++) {
                attn[mi][ni][0] += __expf(acc[mi][ni][0] * 0.125f) * w0;
                attn[mi][ni][1] += __expf(acc[mi][ni][1] * 0.125f) * w0;
                attn[mi][ni][2] += __expf(acc[mi][ni][2] * 0.125f) * w1;
                attn[mi][ni][3] += __expf(acc[mi][ni][3] * 0.125f) * w1;
            }
        }
    }

    #pragma unroll
    for (int mi = 0; mi < 4; mi++) {
        int r = bt * 128 + wm * 64 + mi * 16 + g;
        #pragma unroll
        for (int ni = 0; ni < 4; ni++) {
            int c = bs * 128 + wn * 32 + ni * 8 + tg * 2;
            *(__nv_bfloat162*)&g_attnb[(size_t)r * SRCN + c] =
                __floats2bfloat162_rn(attn[mi][ni][0], attn[mi][ni][1]);
            *(__nv_bfloat162*)&g_attnb[(size_t)(r + 8) * SRCN + c] =
                __floats2bfloat162_rn(attn[mi][ni][2], attn[mi][ni][3]);
        }
    }
}

// ---------------- kernel 5: fused scatter + log_softmax + logaddexp ---------
__global__ void __launch_bounds__(1024) final_kernel(
    const float* __restrict__ logits, const int* __restrict__ ids,
    float* __restrict__ out)
{
    extern __shared__ float smem[];
    float* ext = smem;            // EXTV floats
    float* red = smem + EXTV;     // 32 floats

    const int t    = blockIdx.x;
    const int tid  = threadIdx.x;
    const int lane = tid & 31;
    const int wid  = tid >> 5;

    for (int i = tid; i < EXTV; i += 1024) ext[i] = 0.0f;
    __syncthreads();

    // scatter attn (bf16) into extended-vocab table
    const __nv_bfloat162* ap = (const __nv_bfloat162*)(g_attnb + (size_t)t * SRCN);
    const int2* id2 = (const int2*)ids;
    #pragma unroll
    for (int i = tid; i < SRCN / 2; i += 1024) {
        float2 a = __bfloat1622float2(ap[i]);
        int2   d = id2[i];
        atomicAdd(&ext[d.x], a.x);
        atomicAdd(&ext[d.y], a.y);
    }

    // pass 1: sum of exp over logits (bounded, no max needed)
    const float* lg = logits + (size_t)t * NVOC;
    float ssum = 0.0f;
    for (int i = tid; i < NVOC; i += 1024) ssum += __expf(lg[i]);
    ssum = warp_sum(ssum);
    if (lane == 0) red[wid] = ssum;
    __syncthreads();                 // also fences the scatter atomics
    if (wid == 0) {
        float x = red[lane];
        x = warp_sum(x);
        if (lane == 0) red[0] = x;
    }
    __syncthreads();
    const float lse = __logf(red[0]);

    const float lk    = g_lk[t];
    const float copyp = __expf(g_lc[t]);

    // pass 2: outputs (logits row is L2-hot from pass 1)
    float* op = out + (size_t)t * EXTV;
    for (int v = tid; v < EXTV; v += 1024) {
        float base = (v < NVOC) ? (lg[v] - lse + lk) : -1e9f;
        float e = ext[v];
        op[v] = (e > 0.0f) ? __logf(__expf(base) + e * copyp) : base;
    }
}

// ---------------- host launcher ---------------------------------------------
extern "C" void kernel_launch(void* const* d_in, const int* in_sizes, int n_in,
                              void* d_out, int out_size)
{
    const float* logits = (const float*)d_in[0];
    const int*   ids    = (const int*)d_in[1];
    const float* src    = (const float*)d_in[2];
    const float* tgt    = (const float*)d_in[3];
    const float* w_lin;
    const float* b_lin;
    const float* Wq;
    const float* Wk;
    if (n_in >= 9 && in_sizes[4] == 1) {
        w_lin = (const float*)d_in[5];
        b_lin = (const float*)d_in[6];
        Wq    = (const float*)d_in[7];
        Wk    = (const float*)d_in[8];
    } else {
        w_lin = (const float*)d_in[4];
        b_lin = (const float*)d_in[5];
        Wq    = (const float*)d_in[6];
        Wk    = (const float*)d_in[7];
    }

    static bool            inited = false;
    static __nv_bfloat16*  pQ = nullptr;
    static __nv_bfloat16*  pK = nullptr;
    if (!inited) {
        cudaFuncSetAttribute(final_kernel,
                             cudaFuncAttributeMaxDynamicSharedMemorySize,
                             (EXTV + 32) * (int)sizeof(float));
        void* tmp;
        cudaGetSymbolAddress(&tmp, g_Qb); pQ = (__nv_bfloat16*)tmp;
        cudaGetSymbolAddress(&tmp, g_Kb); pK = (__nv_bfloat16*)tmp;
        inited = true;
    }

    float* out = (float*)d_out;

    // 1) gating scalars
    z_kernel<<<TGTN / 8, 256>>>(tgt, w_lin, b_lin);

    // 2) projections (tf32 mma -> bf16 Q/K)
    proj_gemm_t<<<dim3(DIMN / 128, TGTN / 128), 256>>>(tgt, Wq, pQ);
    proj_gemm_t<<<dim3(DIMN / 128, SRCN / 128), 256>>>(src, Wk, pK);

    // 3) phase A: softmax denominators (bf16 mma recompute, no S materialized)
    phaseA_kernel<<<dim3(TGTN / 128, NHEAD, ZSPLIT), 256>>>();
    combine_kernel<<<(NHEAD * TGTN) / 256, 256>>>();

    // 4) phase B: head-mean attention, single bf16 write
    phaseB_kernel<<<dim3(SRCN / 128, TGTN / 128), 256>>>();

    // 5) fused scatter + log_softmax + combine
    final_kernel<<<TGTN, 1024, (EXTV + 32) * (int)sizeof(float)>>>(logits, ids, out);
}

// round 8
// speedup vs baseline: 1.0069x; 1.0069x over previous
#include <cuda_runtime.h>
#include <cuda_bf16.h>
#include <math.h>
#include <stdint.h>
#include <cstdint>

#define TGTN 2048
#define SRCN 4096
#define DIMN 512
#define NHEAD 8
#define HDIM 64
#define NVOC 32000
#define EXTV 36096

// ---------------- scratch (device globals; no allocation allowed) ----------
__device__ __nv_bfloat16 g_Qb[TGTN * DIMN];                   // 2 MB (L2-resident)
__device__ __nv_bfloat16 g_Kb[SRCN * DIMN];                   // 4 MB (L2-resident)
__device__ __nv_bfloat16 g_Sb[(size_t)NHEAD * TGTN * SRCN];   // 128 MB exp(S/8), bf16
__device__ __nv_bfloat16 g_attnb[(size_t)TGTN * SRCN];        // 16 MB head-mean attn
__device__ float         g_lk[TGTN];                          // log_keep
__device__ float         g_lc[TGTN];                          // log_copy

// ---------------- helpers ---------------------------------------------------
__device__ __forceinline__ float log_sigmoid_f(float x) {
    return fminf(x, 0.0f) - log1pf(expf(-fabsf(x)));
}
__device__ __forceinline__ float warp_sum(float v) {
    #pragma unroll
    for (int o = 16; o > 0; o >>= 1) v += __shfl_xor_sync(0xffffffffu, v, o);
    return v;
}
__device__ __forceinline__ float f2tf32(float x) {
    unsigned u;
    asm("cvt.rna.tf32.f32 %0, %1;" : "=r"(u) : "f"(x));
    return __uint_as_float(u);
}
__device__ __forceinline__ float4 tf32x4(float4 v) {
    v.x = f2tf32(v.x); v.y = f2tf32(v.y); v.z = f2tf32(v.z); v.w = f2tf32(v.w);
    return v;
}
__device__ __forceinline__ void mma_tf32(float* c, const unsigned* a, const unsigned* b) {
    asm volatile(
        "mma.sync.aligned.m16n8k8.row.col.f32.tf32.tf32.f32 "
        "{%0,%1,%2,%3},{%4,%5,%6,%7},{%8,%9},{%0,%1,%2,%3};\n"
        : "+f"(c[0]), "+f"(c[1]), "+f"(c[2]), "+f"(c[3])
        : "r"(a[0]), "r"(a[1]), "r"(a[2]), "r"(a[3]), "r"(b[0]), "r"(b[1]));
}
__device__ __forceinline__ void mma_bf16(float* c, const unsigned* a, const unsigned* b) {
    asm volatile(
        "mma.sync.aligned.m16n8k16.row.col.f32.bf16.bf16.f32 "
        "{%0,%1,%2,%3},{%4,%5,%6,%7},{%8,%9},{%0,%1,%2,%3};\n"
        : "+f"(c[0]), "+f"(c[1]), "+f"(c[2]), "+f"(c[3])
        : "r"(a[0]), "r"(a[1]), "r"(a[2]), "r"(a[3]), "r"(b[0]), "r"(b[1]));
}
__device__ __forceinline__ void ldsm_x4(unsigned& r0, unsigned& r1, unsigned& r2,
                                        unsigned& r3, uint32_t addr) {
    asm volatile("ldmatrix.sync.aligned.m8n8.x4.shared.b16 {%0,%1,%2,%3}, [%4];\n"
                 : "=r"(r0), "=r"(r1), "=r"(r2), "=r"(r3) : "r"(addr));
}

// swizzled 128x64-bf16 tile: row pitch 128B (8 x 16B chunks), chunk ^= (row&7)
__device__ __forceinline__ void load_tile(const __nv_bfloat16* __restrict__ g,
                                          char* sm, int tid) {
    #pragma unroll
    for (int it = 0; it < 4; it++) {
        int row = it * 32 + (tid >> 3);
        int c   = tid & 7;
        uint4 v = *(const uint4*)(g + (size_t)row * DIMN + c * 8);
        *(uint4*)(sm + row * 128 + ((c ^ (row & 7)) * 16)) = v;
    }
}
__device__ __forceinline__ uint32_t tile_addr(uint32_t base, int row0, int k0, int lane) {
    int r     = row0 + (lane & 15);
    int chunk = (k0 >> 3) + (lane >> 4);
    return base + r * 128 + ((chunk ^ (r & 7)) * 16);
}
// acc[4][4][4] += Q_tile(128x64) @ K_tile(128x64)^T  (warp tile 64x32)
__device__ __forceinline__ void mma_tile(float acc[4][4][4], uint32_t qb, uint32_t kb,
                                         int wm, int wn, int lane) {
    #pragma unroll
    for (int k0 = 0; k0 < HDIM; k0 += 16) {
        unsigned a[4][4], b[4][2];
        #pragma unroll
        for (int mi = 0; mi < 4; mi++)
            ldsm_x4(a[mi][0], a[mi][1], a[mi][2], a[mi][3],
                    tile_addr(qb, wm * 64 + mi * 16, k0, lane));
        #pragma unroll
        for (int nj = 0; nj < 2; nj++) {
            unsigned t0, t1, t2, t3;
            ldsm_x4(t0, t1, t2, t3, tile_addr(kb, wn * 32 + nj * 16, k0, lane));
            b[2 * nj][0]     = t0; b[2 * nj][1]     = t2;
            b[2 * nj + 1][0] = t1; b[2 * nj + 1][1] = t3;
        }
        #pragma unroll
        for (int mi = 0; mi < 4; mi++)
            #pragma unroll
            for (int ni = 0; ni < 4; ni++)
                mma_bf16(acc[mi][ni], a[mi], b[ni]);
    }
}

// ---------------- kernel 1: z / log_copy / log_keep -------------------------
__global__ void __launch_bounds__(256) z_kernel(
    const float* __restrict__ tgt, const float* __restrict__ w_lin,
    const float* __restrict__ b_lin)
{
    int row  = blockIdx.x * 8 + (threadIdx.x >> 5);
    int lane = threadIdx.x & 31;
    if (row >= TGTN) return;
    const float* tp = tgt + (size_t)row * DIMN;
    float s = 0.0f;
    #pragma unroll
    for (int i = 0; i < DIMN / 32; i++) s += tp[lane + i * 32] * w_lin[lane + i * 32];
    s = warp_sum(s);
    if (lane == 0) {
        float z = s + b_lin[0];
        g_lc[row] = log_sigmoid_f(z);
        g_lk[row] = log_sigmoid_f(-z);
    }
}

// ---------------- kernel 2: projection GEMM (tf32 mma, bf16 output) ---------
__global__ void __launch_bounds__(256, 2) proj_gemm_t(
    const float* __restrict__ A, const float* __restrict__ W,
    __nv_bfloat16* __restrict__ C)
{
    __shared__ float As[128 * 36];
    __shared__ float Ws[32 * 136];

    const int tid    = threadIdx.x;
    const int lane   = tid & 31;
    const int wid    = tid >> 5;
    const int warp_m = wid & 1;
    const int warp_n = wid >> 1;
    const int g      = lane >> 2;
    const int tg     = lane & 3;
    const int r0     = blockIdx.y * 128;
    const int c0     = blockIdx.x * 128;

    float acc[4][4][4];
    #pragma unroll
    for (int i = 0; i < 4; i++)
        #pragma unroll
        for (int j = 0; j < 4; j++)
            #pragma unroll
            for (int q = 0; q < 4; q++) acc[i][j][q] = 0.0f;

    for (int kc = 0; kc < DIMN; kc += 32) {
        __syncthreads();
        #pragma unroll
        for (int t = 0; t < 4; t++) {
            int idx = tid + t * 256;
            int r = idx >> 3, c4 = idx & 7;
            float4 v = *(const float4*)&A[(size_t)(r0 + r) * DIMN + kc + c4 * 4];
            *(float4*)&As[r * 36 + c4 * 4] = tf32x4(v);
        }
        #pragma unroll
        for (int t = 0; t < 4; t++) {
            int idx = tid + t * 256;
            int kr = idx >> 5, c4 = idx & 31;
            float4 v = *(const float4*)&W[(size_t)(kc + kr) * DIMN + c0 + c4 * 4];
            *(float4*)&Ws[kr * 136 + c4 * 4] = tf32x4(v);
        }
        __syncthreads();

        #pragma unroll
        for (int k0 = 0; k0 < 32; k0 += 8) {
            unsigned a[4][4], b[4][2];
            #pragma unroll
            for (int mi = 0; mi < 4; mi++) {
                int mb = warp_m * 64 + mi * 16;
                a[mi][0] = __float_as_uint(As[(mb + g    ) * 36 + k0 + tg    ]);
                a[mi][1] = __float_as_uint(As[(mb + g + 8) * 36 + k0 + tg    ]);
                a[mi][2] = __float_as_uint(As[(mb + g    ) * 36 + k0 + tg + 4]);
                a[mi][3] = __float_as_uint(As[(mb + g + 8) * 36 + k0 + tg + 4]);
            }
            #pragma unroll
            for (int ni = 0; ni < 4; ni++) {
                int nb = warp_n * 32 + ni * 8;
                b[ni][0] = __float_as_uint(Ws[(k0 + tg    ) * 136 + nb + g]);
                b[ni][1] = __float_as_uint(Ws[(k0 + tg + 4) * 136 + nb + g]);
            }
            #pragma unroll
            for (int mi = 0; mi < 4; mi++)
                #pragma unroll
                for (int ni = 0; ni < 4; ni++)
                    mma_tf32(acc[mi][ni], a[mi], b[ni]);
        }
    }

    #pragma unroll
    for (int mi = 0; mi < 4; mi++) {
        int r = r0 + warp_m * 64 + mi * 16 + g;
        #pragma unroll
        for (int ni = 0; ni < 4; ni++) {
            int c = c0 + warp_n * 32 + ni * 8 + tg * 2;
            *(__nv_bfloat162*)&C[(size_t)r * DIMN + c] =
                __floats2bfloat162_rn(acc[mi][ni][0], acc[mi][ni][1]);
            *(__nv_bfloat162*)&C[(size_t)(r + 8) * DIMN + c] =
                __floats2bfloat162_rn(acc[mi][ni][2], acc[mi][ni][3]);
        }
    }
}

// ---------------- kernel 3: scores -> exp(S/8) bf16 (swizzled ldmatrix mma) -
// grid (32 s-tiles, 16 t-tiles, 8 heads); block 256 (warps 2x4, 64x32 tile).
__global__ void __launch_bounds__(256) scores_exp_kernel()
{
    __shared__ __align__(16) char sQ[128 * 128];
    __shared__ __align__(16) char sK[128 * 128];

    const int tid  = threadIdx.x;
    const int lane = tid & 31;
    const int wid  = tid >> 5;
    const int wm   = wid & 1;
    const int wn   = wid >> 1;
    const int g    = lane >> 2;
    const int tg   = lane & 3;
    const int bs   = blockIdx.x;
    const int bt   = blockIdx.y;
    const int h    = blockIdx.z;

    load_tile(g_Qb + (size_t)(bt * 128) * DIMN + h * HDIM, sQ, tid);
    load_tile(g_Kb + (size_t)(bs * 128) * DIMN + h * HDIM, sK, tid);
    __syncthreads();

    const uint32_t qb = (uint32_t)__cvta_generic_to_shared(sQ);
    const uint32_t kb = (uint32_t)__cvta_generic_to_shared(sK);

    float acc[4][4][4];
    #pragma unroll
    for (int i = 0; i < 4; i++)
        #pragma unroll
        for (int j = 0; j < 4; j++)
            #pragma unroll
            for (int q = 0; q < 4; q++) acc[i][j][q] = 0.0f;
    mma_tile(acc, qb, kb, wm, wn, lane);

    #pragma unroll
    for (int mi = 0; mi < 4; mi++) {
        int r = bt * 128 + wm * 64 + mi * 16 + g;
        size_t base0 = ((size_t)h * TGTN + r) * SRCN;
        size_t base1 = base0 + (size_t)8 * SRCN;
        #pragma unroll
        for (int ni = 0; ni < 4; ni++) {
            int c = bs * 128 + wn * 32 + ni * 8 + tg * 2;
            *(__nv_bfloat162*)&g_Sb[base0 + c] =
                __floats2bfloat162_rn(__expf(acc[mi][ni][0] * 0.125f),
                                      __expf(acc[mi][ni][1] * 0.125f));
            *(__nv_bfloat162*)&g_Sb[base1 + c] =
                __floats2bfloat162_rn(__expf(acc[mi][ni][2] * 0.125f),
                                      __expf(acc[mi][ni][3] * 0.125f));
        }
    }
}

// ---------------- kernel 4: normalize + head-mean (no MUFU) -----------------
// one block per target row t; per head: sum exp-row -> Z_h, accumulate
// expv * (0.125/Z_h) into registers; single bf16 write of head-mean attn.
__global__ void __launch_bounds__(256) norm_kernel()
{
    __shared__ float red[8];
    const int t    = blockIdx.x;
    const int tid  = threadIdx.x;
    const int lane = tid & 31;
    const int wid  = tid >> 5;

    float accr[16];
    #pragma unroll
    for (int j = 0; j < 16; j++) accr[j] = 0.0f;

    for (int h = 0; h < NHEAD; h++) {
        const __nv_bfloat162* sp =
            (const __nv_bfloat162*)(g_Sb + ((size_t)h * TGTN + t) * SRCN);
        float v[16];
        float s = 0.0f;
        #pragma unroll
        for (int j = 0; j < 8; j++) {
            float2 w = __bfloat1622float2(sp[tid + j * 256]);
            v[2 * j] = w.x; v[2 * j + 1] = w.y;
            s += w.x + w.y;
        }
        s = warp_sum(s);
        if (lane == 0) red[wid] = s;
        __syncthreads();
        float tot = 0.0f;
        #pragma unroll
        for (int w = 0; w < 8; w++) tot += red[w];
        __syncthreads();

        float inv = 0.125f / tot;
        #pragma unroll
        for (int j = 0; j < 16; j++) accr[j] += v[j] * inv;
    }
    __nv_bfloat162* ap = (__nv_bfloat162*)(g_attnb + (size_t)t * SRCN);
    #pragma unroll
    for (int j = 0; j < 8; j++)
        ap[tid + j * 256] = __floats2bfloat162_rn(accr[2 * j], accr[2 * j + 1]);
}

// ---------------- kernel 5: fused scatter + log_softmax + logaddexp ---------
// smem: ext[EXTV] f32 scatter table + lgb[NVOC] bf16 logits cache + red[32].
__global__ void __launch_bounds__(1024) final_kernel(
    const float* __restrict__ logits, const int* __restrict__ ids,
    float* __restrict__ out)
{
    extern __shared__ float smem[];
    float*         ext = smem;                                  // EXTV f32
    __nv_bfloat16* lgb = (__nv_bfloat16*)(smem + EXTV);         // NVOC bf16
    float*         red = (float*)(lgb + NVOC);                  // 32 f32

    const int t    = blockIdx.x;
    const int tid  = threadIdx.x;
    const int lane = tid & 31;
    const int wid  = tid >> 5;

    for (int i = tid; i < EXTV; i += 1024) ext[i] = 0.0f;
    __syncthreads();

    // scatter attn (bf16) into extended-vocab table
    const __nv_bfloat162* ap = (const __nv_bfloat162*)(g_attnb + (size_t)t * SRCN);
    const int2* id2 = (const int2*)ids;
    #pragma unroll
    for (int i = tid; i < SRCN / 2; i += 1024) {
        float2 a = __bfloat1622float2(ap[i]);
        int2   d = id2[i];
        atomicAdd(&ext[d.x], a.x);
        atomicAdd(&ext[d.y], a.y);
    }

    // pass 1: sum of exp over logits (bounded, no max needed); stash bf16 copy
    const float* lg = logits + (size_t)t * NVOC;
    float ssum = 0.0f;
    for (int i = tid; i < NVOC; i += 1024) {
        float x = lg[i];
        lgb[i] = __float2bfloat16(x);
        ssum += __expf(x);
    }
    ssum = warp_sum(ssum);
    if (lane == 0) red[wid] = ssum;
    __syncthreads();                 // also fences the scatter atomics
    if (wid == 0) {
        float x = red[lane];
        x = warp_sum(x);
        if (lane == 0) red[0] = x;
    }
    __syncthreads();
    const float lse = __logf(red[0]);

    const float lk    = g_lk[t];
    const float copyp = __expf(g_lc[t]);

    // pass 2: outputs; logits come from the smem bf16 cache
    float* op = out + (size_t)t * EXTV;
    for (int v = tid; v < EXTV; v += 1024) {
        float base = (v < NVOC) ? (__bfloat162float(lgb[v]) - lse + lk) : -1e9f;
        float e = ext[v];
        op[v] = (e > 0.0f) ? __logf(__expf(base) + e * copyp) : base;
    }
}

// ---------------- host launcher ---------------------------------------------
extern "C" void kernel_launch(void* const* d_in, const int* in_sizes, int n_in,
                              void* d_out, int out_size)
{
    const float* logits = (const float*)d_in[0];
    const int*   ids    = (const int*)d_in[1];
    const float* src    = (const float*)d_in[2];
    const float* tgt    = (const float*)d_in[3];
    const float* w_lin;
    const float* b_lin;
    const float* Wq;
    const float* Wk;
    if (n_in >= 9 && in_sizes[4] == 1) {
        w_lin = (const float*)d_in[5];
        b_lin = (const float*)d_in[6];
        Wq    = (const float*)d_in[7];
        Wk    = (const float*)d_in[8];
    } else {
        w_lin = (const float*)d_in[4];
        b_lin = (const float*)d_in[5];
        Wq    = (const float*)d_in[6];
        Wk    = (const float*)d_in[7];
    }

    static const int FINAL_SMEM = EXTV * 4 + NVOC * 2 + 128;   // 208,512 B

    static bool            inited = false;
    static __nv_bfloat16*  pQ = nullptr;
    static __nv_bfloat16*  pK = nullptr;
    if (!inited) {
        cudaFuncSetAttribute(final_kernel,
                             cudaFuncAttributeMaxDynamicSharedMemorySize,
                             FINAL_SMEM);
        void* tmp;
        cudaGetSymbolAddress(&tmp, g_Qb); pQ = (__nv_bfloat16*)tmp;
        cudaGetSymbolAddress(&tmp, g_Kb); pK = (__nv_bfloat16*)tmp;
        inited = true;
    }

    float* out = (float*)d_out;

    // 1) gating scalars
    z_kernel<<<TGTN / 8, 256>>>(tgt, w_lin, b_lin);

    // 2) projections (tf32 mma -> bf16 Q/K)
    proj_gemm_t<<<dim3(DIMN / 128, TGTN / 128), 256>>>(tgt, Wq, pQ);
    proj_gemm_t<<<dim3(DIMN / 128, SRCN / 128), 256>>>(src, Wk, pK);

    // 3) per-head exp-scores (bf16 mma + swizzled ldmatrix -> bf16 exp store)
    scores_exp_kernel<<<dim3(SRCN / 128, TGTN / 128, NHEAD), 256>>>();

    // 4) normalize + head mean (pure sums, single 16MB bf16 write)
    norm_kernel<<<TGTN, 256>>>();

    // 5) fused scatter + log_softmax + combine
    final_kernel<<<TGTN, 1024, FINAL_SMEM>>>(logits, ids, out);
}

// round 9
// speedup vs baseline: 1.2888x; 1.2799x over previous
#include <cuda_runtime.h>
#include <cuda_bf16.h>
#include <math.h>
#include <stdint.h>
#include <cstdint>

#define TGTN 2048
#define SRCN 4096
#define DIMN 512
#define NHEAD 8
#define HDIM 64
#define NVOC 32000
#define EXTV 36096

// ---------------- scratch (device globals; no allocation allowed) ----------
__device__ __nv_bfloat16 g_Qb[TGTN * DIMN];                   // 2 MB (L2-resident)
__device__ __nv_bfloat16 g_Kb[SRCN * DIMN];                   // 4 MB (L2-resident)
__device__ __nv_bfloat16 g_Sb[(size_t)NHEAD * TGTN * SRCN];   // 128 MB exp(S/8), bf16
__device__ float         g_Z[NHEAD * TGTN];                   // softmax denominators
__device__ float         g_lk[TGTN];                          // log_keep
__device__ float         g_lc[TGTN];                          // log_copy

// ---------------- helpers ---------------------------------------------------
__device__ __forceinline__ float log_sigmoid_f(float x) {
    return fminf(x, 0.0f) - log1pf(expf(-fabsf(x)));
}
__device__ __forceinline__ float warp_sum(float v) {
    #pragma unroll
    for (int o = 16; o > 0; o >>= 1) v += __shfl_xor_sync(0xffffffffu, v, o);
    return v;
}
__device__ __forceinline__ float f2tf32(float x) {
    unsigned u;
    asm("cvt.rna.tf32.f32 %0, %1;" : "=r"(u) : "f"(x));
    return __uint_as_float(u);
}
__device__ __forceinline__ float4 tf32x4(float4 v) {
    v.x = f2tf32(v.x); v.y = f2tf32(v.y); v.z = f2tf32(v.z); v.w = f2tf32(v.w);
    return v;
}
__device__ __forceinline__ void mma_tf32(float* c, const unsigned* a, const unsigned* b) {
    asm volatile(
        "mma.sync.aligned.m16n8k8.row.col.f32.tf32.tf32.f32 "
        "{%0,%1,%2,%3},{%4,%5,%6,%7},{%8,%9},{%0,%1,%2,%3};\n"
        : "+f"(c[0]), "+f"(c[1]), "+f"(c[2]), "+f"(c[3])
        : "r"(a[0]), "r"(a[1]), "r"(a[2]), "r"(a[3]), "r"(b[0]), "r"(b[1]));
}
__device__ __forceinline__ void mma_bf16(float* c, const unsigned* a, const unsigned* b) {
    asm volatile(
        "mma.sync.aligned.m16n8k16.row.col.f32.bf16.bf16.f32 "
        "{%0,%1,%2,%3},{%4,%5,%6,%7},{%8,%9},{%0,%1,%2,%3};\n"
        : "+f"(c[0]), "+f"(c[1]), "+f"(c[2]), "+f"(c[3])
        : "r"(a[0]), "r"(a[1]), "r"(a[2]), "r"(a[3]), "r"(b[0]), "r"(b[1]));
}
__device__ __forceinline__ void ldsm_x4(unsigned& r0, unsigned& r1, unsigned& r2,
                                        unsigned& r3, uint32_t addr) {
    asm volatile("ldmatrix.sync.aligned.m8n8.x4.shared.b16 {%0,%1,%2,%3}, [%4];\n"
                 : "=r"(r0), "=r"(r1), "=r"(r2), "=r"(r3) : "r"(addr));
}

// swizzled 128x64-bf16 tile: row pitch 128B (8 x 16B chunks), chunk ^= (row&7)
__device__ __forceinline__ void load_tile(const __nv_bfloat16* __restrict__ g,
                                          char* sm, int tid) {
    #pragma unroll
    for (int it = 0; it < 4; it++) {
        int row = it * 32 + (tid >> 3);
        int c   = tid & 7;
        uint4 v = *(const uint4*)(g + (size_t)row * DIMN + c * 8);
        *(uint4*)(sm + row * 128 + ((c ^ (row & 7)) * 16)) = v;
    }
}
__device__ __forceinline__ uint32_t tile_addr(uint32_t base, int row0, int k0, int lane) {
    int r     = row0 + (lane & 15);
    int chunk = (k0 >> 3) + (lane >> 4);
    return base + r * 128 + ((chunk ^ (r & 7)) * 16);
}
// acc[4][4][4] += Q_tile(128x64) @ K_tile(128x64)^T  (warp tile 64x32)
__device__ __forceinline__ void mma_tile(float acc[4][4][4], uint32_t qb, uint32_t kb,
                                         int wm, int wn, int lane) {
    #pragma unroll
    for (int k0 = 0; k0 < HDIM; k0 += 16) {
        unsigned a[4][4], b[4][2];
        #pragma unroll
        for (int mi = 0; mi < 4; mi++)
            ldsm_x4(a[mi][0], a[mi][1], a[mi][2], a[mi][3],
                    tile_addr(qb, wm * 64 + mi * 16, k0, lane));
        #pragma unroll
        for (int nj = 0; nj < 2; nj++) {
            unsigned t0, t1, t2, t3;
            ldsm_x4(t0, t1, t2, t3, tile_addr(kb, wn * 32 + nj * 16, k0, lane));
            b[2 * nj][0]     = t0; b[2 * nj][1]     = t2;
            b[2 * nj + 1][0] = t1; b[2 * nj + 1][1] = t3;
        }
        #pragma unroll
        for (int mi = 0; mi < 4; mi++)
            #pragma unroll
            for (int ni = 0; ni < 4; ni++)
                mma_bf16(acc[mi][ni], a[mi], b[ni]);
    }
}

// ---------------- kernel 1: z / log_copy / log_keep -------------------------
__global__ void __launch_bounds__(256) z_kernel(
    const float* __restrict__ tgt, const float* __restrict__ w_lin,
    const float* __restrict__ b_lin)
{
    int row  = blockIdx.x * 8 + (threadIdx.x >> 5);
    int lane = threadIdx.x & 31;
    if (row >= TGTN) return;
    const float* tp = tgt + (size_t)row * DIMN;
    float s = 0.0f;
    #pragma unroll
    for (int i = 0; i < DIMN / 32; i++) s += tp[lane + i * 32] * w_lin[lane + i * 32];
    s = warp_sum(s);
    if (lane == 0) {
        float z = s + b_lin[0];
        g_lc[row] = log_sigmoid_f(z);
        g_lk[row] = log_sigmoid_f(-z);
    }
}

// ---------------- kernel 1b: zero the Z accumulators ------------------------
__global__ void __launch_bounds__(1024) zeroZ_kernel()
{
    g_Z[blockIdx.x * 1024 + threadIdx.x] = 0.0f;
}

// ---------------- kernel 2: projection GEMM (tf32 mma, bf16 output) ---------
__global__ void __launch_bounds__(256, 2) proj_gemm_t(
    const float* __restrict__ A, const float* __restrict__ W,
    __nv_bfloat16* __restrict__ C)
{
    __shared__ float As[128 * 36];
    __shared__ float Ws[32 * 136];

    const int tid    = threadIdx.x;
    const int lane   = tid & 31;
    const int wid    = tid >> 5;
    const int warp_m = wid & 1;
    const int warp_n = wid >> 1;
    const int g      = lane >> 2;
    const int tg     = lane & 3;
    const int r0     = blockIdx.y * 128;
    const int c0     = blockIdx.x * 128;

    float acc[4][4][4];
    #pragma unroll
    for (int i = 0; i < 4; i++)
        #pragma unroll
        for (int j = 0; j < 4; j++)
            #pragma unroll
            for (int q = 0; q < 4; q++) acc[i][j][q] = 0.0f;

    for (int kc = 0; kc < DIMN; kc += 32) {
        __syncthreads();
        #pragma unroll
        for (int t = 0; t < 4; t++) {
            int idx = tid + t * 256;
            int r = idx >> 3, c4 = idx & 7;
            float4 v = *(const float4*)&A[(size_t)(r0 + r) * DIMN + kc + c4 * 4];
            *(float4*)&As[r * 36 + c4 * 4] = tf32x4(v);
        }
        #pragma unroll
        for (int t = 0; t < 4; t++) {
            int idx = tid + t * 256;
            int kr = idx >> 5, c4 = idx & 31;
            float4 v = *(const float4*)&W[(size_t)(kc + kr) * DIMN + c0 + c4 * 4];
            *(float4*)&Ws[kr * 136 + c4 * 4] = tf32x4(v);
        }
        __syncthreads();

        #pragma unroll
        for (int k0 = 0; k0 < 32; k0 += 8) {
            unsigned a[4][4], b[4][2];
            #pragma unroll
            for (int mi = 0; mi < 4; mi++) {
                int mb = warp_m * 64 + mi * 16;
                a[mi][0] = __float_as_uint(As[(mb + g    ) * 36 + k0 + tg    ]);
                a[mi][1] = __float_as_uint(As[(mb + g + 8) * 36 + k0 + tg    ]);
                a[mi][2] = __float_as_uint(As[(mb + g    ) * 36 + k0 + tg + 4]);
                a[mi][3] = __float_as_uint(As[(mb + g + 8) * 36 + k0 + tg + 4]);
            }
            #pragma unroll
            for (int ni = 0; ni < 4; ni++) {
                int nb = warp_n * 32 + ni * 8;
                b[ni][0] = __float_as_uint(Ws[(k0 + tg    ) * 136 + nb + g]);
                b[ni][1] = __float_as_uint(Ws[(k0 + tg + 4) * 136 + nb + g]);
            }
            #pragma unroll
            for (int mi = 0; mi < 4; mi++)
                #pragma unroll
                for (int ni = 0; ni < 4; ni++)
                    mma_tf32(acc[mi][ni], a[mi], b[ni]);
        }
    }

    #pragma unroll
    for (int mi = 0; mi < 4; mi++) {
        int r = r0 + warp_m * 64 + mi * 16 + g;
        #pragma unroll
        for (int ni = 0; ni < 4; ni++) {
            int c = c0 + warp_n * 32 + ni * 8 + tg * 2;
            *(__nv_bfloat162*)&C[(size_t)r * DIMN + c] =
                __floats2bfloat162_rn(acc[mi][ni][0], acc[mi][ni][1]);
            *(__nv_bfloat162*)&C[(size_t)(r + 8) * DIMN + c] =
                __floats2bfloat162_rn(acc[mi][ni][2], acc[mi][ni][3]);
        }
    }
}

// ---------------- kernel 3: scores -> exp(S/8) bf16 + Z row sums ------------
// grid (32 s-tiles, 16 t-tiles, 8 heads); block 256 (warps 2x4, 64x32 tile).
__global__ void __launch_bounds__(256) scores_exp_kernel()
{
    __shared__ __align__(16) char sQ[128 * 128];
    __shared__ __align__(16) char sK[128 * 128];
    __shared__ float zrow[128];

    const int tid  = threadIdx.x;
    const int lane = tid & 31;
    const int wid  = tid >> 5;
    const int wm   = wid & 1;
    const int wn   = wid >> 1;
    const int g    = lane >> 2;
    const int tg   = lane & 3;
    const int bs   = blockIdx.x;
    const int bt   = blockIdx.y;
    const int h    = blockIdx.z;

    load_tile(g_Qb + (size_t)(bt * 128) * DIMN + h * HDIM, sQ, tid);
    load_tile(g_Kb + (size_t)(bs * 128) * DIMN + h * HDIM, sK, tid);
    if (tid < 128) zrow[tid] = 0.0f;
    __syncthreads();

    const uint32_t qb = (uint32_t)__cvta_generic_to_shared(sQ);
    const uint32_t kb = (uint32_t)__cvta_generic_to_shared(sK);

    float acc[4][4][4];
    #pragma unroll
    for (int i = 0; i < 4; i++)
        #pragma unroll
        for (int j = 0; j < 4; j++)
            #pragma unroll
            for (int q = 0; q < 4; q++) acc[i][j][q] = 0.0f;
    mma_tile(acc, qb, kb, wm, wn, lane);

    float zacc[4][2];
    #pragma unroll
    for (int mi = 0; mi < 4; mi++) { zacc[mi][0] = 0.0f; zacc[mi][1] = 0.0f; }

    #pragma unroll
    for (int mi = 0; mi < 4; mi++) {
        int r = bt * 128 + wm * 64 + mi * 16 + g;
        size_t base0 = ((size_t)h * TGTN + r) * SRCN;
        size_t base1 = base0 + (size_t)8 * SRCN;
        #pragma unroll
        for (int ni = 0; ni < 4; ni++) {
            int c = bs * 128 + wn * 32 + ni * 8 + tg * 2;
            float e0 = __expf(acc[mi][ni][0] * 0.125f);
            float e1 = __expf(acc[mi][ni][1] * 0.125f);
            float e2 = __expf(acc[mi][ni][2] * 0.125f);
            float e3 = __expf(acc[mi][ni][3] * 0.125f);
            *(__nv_bfloat162*)&g_Sb[base0 + c] = __floats2bfloat162_rn(e0, e1);
            *(__nv_bfloat162*)&g_Sb[base1 + c] = __floats2bfloat162_rn(e2, e3);
            zacc[mi][0] += e0 + e1;
            zacc[mi][1] += e2 + e3;
        }
    }

    // reduce row partials: sum over tg (lanes differing in bits 0-1), then smem
    #pragma unroll
    for (int mi = 0; mi < 4; mi++)
        #pragma unroll
        for (int half = 0; half < 2; half++) {
            float v = zacc[mi][half];
            v += __shfl_xor_sync(0xffffffffu, v, 1);
            v += __shfl_xor_sync(0xffffffffu, v, 2);
            if (tg == 0) atomicAdd(&zrow[wm * 64 + mi * 16 + half * 8 + g], v);
        }
    __syncthreads();
    if (tid < 128)
        atomicAdd(&g_Z[h * TGTN + bt * 128 + tid], zrow[tid]);
}

// ---------------- kernel 4: fused attn-combine + scatter + softmax + mix ----
// one block per target row t; smem = bf16 ext table (72KB) -> 2 CTAs/SM.
// attn(t,s) = sum_h expv_h(t,s) * (0.125/Z_h(t)) computed on the fly.
__global__ void __launch_bounds__(1024, 2) final_kernel(
    const float* __restrict__ logits, const int* __restrict__ ids,
    float* __restrict__ out)
{
    extern __shared__ char smraw[];
    __nv_bfloat162* ext2 = (__nv_bfloat162*)smraw;              // EXTV/2 pairs
    float* red = (float*)(smraw + EXTV * 2);                    // 32
    float* wsh = red + 32;                                      // 8

    const int t    = blockIdx.x;
    const int tid  = threadIdx.x;
    const int lane = tid & 31;
    const int wid  = tid >> 5;

    // zero ext table (vectorized: 72192 B / 16 = 4512 uint4)
    {
        uint4 z4 = make_uint4(0u, 0u, 0u, 0u);
        uint4* e4 = (uint4*)smraw;
        for (int i = tid; i < EXTV * 2 / 16; i += 1024) e4[i] = z4;
    }
    if (tid < NHEAD) wsh[tid] = 0.125f / g_Z[tid * TGTN + t];
    __syncthreads();

    // scatter: combine heads on the fly, bf16x2 atomic into ext table
    const int2* id2 = (const int2*)ids;
    for (int i = tid; i < SRCN / 2; i += 1024) {
        float a0 = 0.0f, a1 = 0.0f;
        #pragma unroll
        for (int h = 0; h < NHEAD; h++) {
            const __nv_bfloat162* sp =
                (const __nv_bfloat162*)(g_Sb + ((size_t)h * TGTN + t) * SRCN);
            float2 v = __bfloat1622float2(sp[i]);
            float wh = wsh[h];
            a0 = fmaf(v.x, wh, a0);
            a1 = fmaf(v.y, wh, a1);
        }
        int2 d = id2[i];
        atomicAdd(&ext2[d.x >> 1],
                  (d.x & 1) ? __floats2bfloat162_rn(0.0f, a0)
                            : __floats2bfloat162_rn(a0, 0.0f));
        atomicAdd(&ext2[d.y >> 1],
                  (d.y & 1) ? __floats2bfloat162_rn(0.0f, a1)
                            : __floats2bfloat162_rn(a1, 0.0f));
    }

    // pass 1: sum of exp over logits (bounded, no max needed)
    const float* lg = logits + (size_t)t * NVOC;
    float ssum = 0.0f;
    for (int i = tid; i < NVOC; i += 1024) ssum += __expf(lg[i]);
    ssum = warp_sum(ssum);
    if (lane == 0) red[wid] = ssum;
    __syncthreads();                 // also fences the scatter atomics
    if (wid == 0) {
        float x = red[lane];
        x = warp_sum(x);
        if (lane == 0) red[0] = x;
    }
    __syncthreads();
    const float lse = __logf(red[0]);

    const float lk    = g_lk[t];
    const float copyp = __expf(g_lc[t]);

    // pass 2: outputs (logits row is L2-hot from pass 1)
    const __nv_bfloat16* ext = (const __nv_bfloat16*)smraw;
    float* op = out + (size_t)t * EXTV;
    for (int v = tid; v < EXTV; v += 1024) {
        float base = (v < NVOC) ? (lg[v] - lse + lk) : -1e9f;
        float e = __bfloat162float(ext[v]);
        op[v] = (e > 0.0f) ? __logf(__expf(base) + e * copyp) : base;
    }
}

// ---------------- host launcher ---------------------------------------------
extern "C" void kernel_launch(void* const* d_in, const int* in_sizes, int n_in,
                              void* d_out, int out_size)
{
    const float* logits = (const float*)d_in[0];
    const int*   ids    = (const int*)d_in[1];
    const float* src    = (const float*)d_in[2];
    const float* tgt    = (const float*)d_in[3];
    const float* w_lin;
    const float* b_lin;
    const float* Wq;
    const float* Wk;
    if (n_in >= 9 && in_sizes[4] == 1) {
        w_lin = (const float*)d_in[5];
        b_lin = (const float*)d_in[6];
        Wq    = (const float*)d_in[7];
        Wk    = (const float*)d_in[8];
    } else {
        w_lin = (const float*)d_in[4];
        b_lin = (const float*)d_in[5];
        Wq    = (const float*)d_in[6];
        Wk    = (const float*)d_in[7];
    }

    static const int FINAL_SMEM = EXTV * 2 + 40 * 4;   // 72,352 B

    static bool            inited = false;
    static __nv_bfloat16*  pQ = nullptr;
    static __nv_bfloat16*  pK = nullptr;
    if (!inited) {
        cudaFuncSetAttribute(final_kernel,
                             cudaFuncAttributeMaxDynamicSharedMemorySize,
                             FINAL_SMEM);
        void* tmp;
        cudaGetSymbolAddress(&tmp, g_Qb); pQ = (__nv_bfloat16*)tmp;
        cudaGetSymbolAddress(&tmp, g_Kb); pK = (__nv_bfloat16*)tmp;
        inited = true;
    }

    float* out = (float*)d_out;

    // 1) gating scalars + Z zeroing
    z_kernel<<<TGTN / 8, 256>>>(tgt, w_lin, b_lin);
    zeroZ_kernel<<<(NHEAD * TGTN) / 1024, 1024>>>();

    // 2) projections (tf32 mma -> bf16 Q/K)
    proj_gemm_t<<<dim3(DIMN / 128, TGTN / 128), 256>>>(tgt, Wq, pQ);
    proj_gemm_t<<<dim3(DIMN / 128, SRCN / 128), 256>>>(src, Wk, pK);

    // 3) per-head exp-scores + Z row sums
    scores_exp_kernel<<<dim3(SRCN / 128, TGTN / 128, NHEAD), 256>>>();

    // 4) fused head-combine + scatter + log_softmax + logaddexp
    final_kernel<<<TGTN, 1024, FINAL_SMEM>>>(logits, ids, out);
}

// round 10
// speedup vs baseline: 1.5025x; 1.1658x over previous
#include <cuda_runtime.h>
#include <cuda_bf16.h>
#include <math.h>
#include <stdint.h>
#include <cstdint>

#define TGTN 2048
#define SRCN 4096
#define DIMN 512
#define NHEAD 8
#define HDIM 64
#define NVOC 32000
#define EXTV 36096

// ---------------- scratch (device globals; no allocation allowed) ----------
__device__ __nv_bfloat16 g_Qb[TGTN * DIMN];                   // 2 MB (L2-resident)
__device__ __nv_bfloat16 g_Kb[SRCN * DIMN];                   // 4 MB (L2-resident)
__device__ __nv_bfloat16 g_Sb[(size_t)NHEAD * TGTN * SRCN];   // 128 MB exp(S/8), bf16
__device__ float         g_Z[NHEAD * TGTN];                   // softmax denominators
__device__ float         g_lk[TGTN];                          // log_keep
__device__ float         g_lc[TGTN];                          // log_copy

// ---------------- helpers ---------------------------------------------------
__device__ __forceinline__ float log_sigmoid_f(float x) {
    return fminf(x, 0.0f) - log1pf(expf(-fabsf(x)));
}
__device__ __forceinline__ float warp_sum(float v) {
    #pragma unroll
    for (int o = 16; o > 0; o >>= 1) v += __shfl_xor_sync(0xffffffffu, v, o);
    return v;
}
__device__ __forceinline__ void cp16(uint32_t sm, const void* g) {
    asm volatile("cp.async.cg.shared.global [%0], [%1], 16;\n" :: "r"(sm), "l"(g));
}
#define CP_COMMIT() asm volatile("cp.async.commit_group;\n" ::: "memory")
#define CP_WAIT0()  asm volatile("cp.async.wait_group 0;\n" ::: "memory")

__device__ __forceinline__ void mma_tf32(float* c, const unsigned* a, const unsigned* b) {
    asm volatile(
        "mma.sync.aligned.m16n8k8.row.col.f32.tf32.tf32.f32 "
        "{%0,%1,%2,%3},{%4,%5,%6,%7},{%8,%9},{%0,%1,%2,%3};\n"
        : "+f"(c[0]), "+f"(c[1]), "+f"(c[2]), "+f"(c[3])
        : "r"(a[0]), "r"(a[1]), "r"(a[2]), "r"(a[3]), "r"(b[0]), "r"(b[1]));
}
__device__ __forceinline__ void mma_bf16(float* c, const unsigned* a, const unsigned* b) {
    asm volatile(
        "mma.sync.aligned.m16n8k16.row.col.f32.bf16.bf16.f32 "
        "{%0,%1,%2,%3},{%4,%5,%6,%7},{%8,%9},{%0,%1,%2,%3};\n"
        : "+f"(c[0]), "+f"(c[1]), "+f"(c[2]), "+f"(c[3])
        : "r"(a[0]), "r"(a[1]), "r"(a[2]), "r"(a[3]), "r"(b[0]), "r"(b[1]));
}
__device__ __forceinline__ void ldsm_x4(unsigned& r0, unsigned& r1, unsigned& r2,
                                        unsigned& r3, uint32_t addr) {
    asm volatile("ldmatrix.sync.aligned.m8n8.x4.shared.b16 {%0,%1,%2,%3}, [%4];\n"
                 : "=r"(r0), "=r"(r1), "=r"(r2), "=r"(r3) : "r"(addr));
}

// swizzled 128x64-bf16 tile via cp.async: row pitch 128B, chunk ^= (row&7)
__device__ __forceinline__ void load_tile_ca(const __nv_bfloat16* __restrict__ g,
                                             uint32_t smBase, int tid) {
    #pragma unroll
    for (int it = 0; it < 4; it++) {
        int row = it * 32 + (tid >> 3);
        int c   = tid & 7;
        cp16(smBase + row * 128 + ((c ^ (row & 7)) * 16),
             g + (size_t)row * DIMN + c * 8);
    }
}
__device__ __forceinline__ uint32_t tile_addr(uint32_t base, int row0, int k0, int lane) {
    int r     = row0 + (lane & 15);
    int chunk = (k0 >> 3) + (lane >> 4);
    return base + r * 128 + ((chunk ^ (r & 7)) * 16);
}
// acc[4][4][4] += Q_tile(128x64) @ K_tile(128x64)^T  (warp tile 64x32)
__device__ __forceinline__ void mma_tile(float acc[4][4][4], uint32_t qb, uint32_t kb,
                                         int wm, int wn, int lane) {
    #pragma unroll
    for (int k0 = 0; k0 < HDIM; k0 += 16) {
        unsigned a[4][4], b[4][2];
        #pragma unroll
        for (int mi = 0; mi < 4; mi++)
            ldsm_x4(a[mi][0], a[mi][1], a[mi][2], a[mi][3],
                    tile_addr(qb, wm * 64 + mi * 16, k0, lane));
        #pragma unroll
        for (int nj = 0; nj < 2; nj++) {
            unsigned t0, t1, t2, t3;
            ldsm_x4(t0, t1, t2, t3, tile_addr(kb, wn * 32 + nj * 16, k0, lane));
            b[2 * nj][0]     = t0; b[2 * nj][1]     = t2;
            b[2 * nj + 1][0] = t1; b[2 * nj + 1][1] = t3;
        }
        #pragma unroll
        for (int mi = 0; mi < 4; mi++)
            #pragma unroll
            for (int ni = 0; ni < 4; ni++)
                mma_bf16(acc[mi][ni], a[mi], b[ni]);
    }
}

// ---------------- kernel 1: z / log_copy / log_keep + zero Z ----------------
__global__ void __launch_bounds__(256) z_kernel(
    const float* __restrict__ tgt, const float* __restrict__ w_lin,
    const float* __restrict__ b_lin)
{
    int gidx = blockIdx.x * 256 + threadIdx.x;
    if (gidx < NHEAD * TGTN) g_Z[gidx] = 0.0f;

    int row  = blockIdx.x * 8 + (threadIdx.x >> 5);
    int lane = threadIdx.x & 31;
    if (row >= TGTN) return;
    const float* tp = tgt + (size_t)row * DIMN;
    float s = 0.0f;
    #pragma unroll
    for (int i = 0; i < DIMN / 32; i++) s += tp[lane + i * 32] * w_lin[lane + i * 32];
    s = warp_sum(s);
    if (lane == 0) {
        float z = s + b_lin[0];
        g_lc[row] = log_sigmoid_f(z);
        g_lk[row] = log_sigmoid_f(-z);
    }
}

// ---------------- kernel 2: fused projection GEMMs (tf32 mma, cp.async) -----
// grid (4, 48): y<16 -> Q tiles (tgt@Wq), y>=16 -> K tiles (src@Wk).
// 128x128 block tile, k-chunk 32, 2-stage cp.async pipeline.
// fp32 fed to tf32 mma without rounding (truncation; within precision slack).
__global__ void __launch_bounds__(256, 2) proj_gemm_fused(
    const float* __restrict__ tgt, const float* __restrict__ src,
    const float* __restrict__ Wq,  const float* __restrict__ Wk,
    __nv_bfloat16* __restrict__ pQ, __nv_bfloat16* __restrict__ pK)
{
    __shared__ float As[2][128 * 36];   // [m][k], row pitch 144B (16B-mult)
    __shared__ float Ws[2][32 * 136];   // [k][n], row pitch 544B (16B-mult)

    const bool isK = blockIdx.y >= 16;
    const float* A = isK ? src : tgt;
    const float* W = isK ? Wk  : Wq;
    __nv_bfloat16* C = isK ? pK : pQ;
    const int r0 = (isK ? (blockIdx.y - 16) : blockIdx.y) * 128;
    const int c0 = blockIdx.x * 128;

    const int tid    = threadIdx.x;
    const int lane   = tid & 31;
    const int wid    = tid >> 5;
    const int warp_m = wid & 1;
    const int warp_n = wid >> 1;
    const int g      = lane >> 2;
    const int tg     = lane & 3;

    const uint32_t asB = (uint32_t)__cvta_generic_to_shared(&As[0][0]);
    const uint32_t wsB = (uint32_t)__cvta_generic_to_shared(&Ws[0][0]);
    const uint32_t asPitch = 128 * 36 * 4;   // bytes per buffer
    const uint32_t wsPitch = 32 * 136 * 4;

    // per-thread load coords
    const int ar  = tid >> 3, ac4 = tid & 7;      // A: 32 rows per step of 256
    const int wkr = tid >> 5, wc4 = tid & 31;     // W: 8 k-rows per step

    // prefetch chunk 0 into buffer 0
    {
        #pragma unroll
        for (int t = 0; t < 4; t++) {
            int r = ar + t * 32;
            cp16(asB + r * 144 + ac4 * 16, &A[(size_t)(r0 + r) * DIMN + ac4 * 4]);
        }
        #pragma unroll
        for (int t = 0; t < 4; t++) {
            int kr = wkr + t * 8;
            cp16(wsB + kr * 544 + wc4 * 16, &W[(size_t)kr * DIMN + c0 + wc4 * 4]);
        }
        CP_COMMIT();
    }

    float acc[4][4][4];
    #pragma unroll
    for (int i = 0; i < 4; i++)
        #pragma unroll
        for (int j = 0; j < 4; j++)
            #pragma unroll
            for (int q = 0; q < 4; q++) acc[i][j][q] = 0.0f;

    #pragma unroll 1
    for (int it = 0; it < DIMN / 32; it++) {
        CP_WAIT0();
        __syncthreads();
        const int cur = it & 1;

        if (it + 1 < DIMN / 32) {
            const int nxt = cur ^ 1;
            const int kc  = (it + 1) * 32;
            #pragma unroll
            for (int t = 0; t < 4; t++) {
                int r = ar + t * 32;
                cp16(asB + nxt * asPitch + r * 144 + ac4 * 16,
                     &A[(size_t)(r0 + r) * DIMN + kc + ac4 * 4]);
            }
            #pragma unroll
            for (int t = 0; t < 4; t++) {
                int kr = wkr + t * 8;
                cp16(wsB + nxt * wsPitch + kr * 544 + wc4 * 16,
                     &W[(size_t)(kc + kr) * DIMN + c0 + wc4 * 4]);
            }
            CP_COMMIT();
        }

        const float* Ab = As[cur];
        const float* Wb = Ws[cur];
        #pragma unroll
        for (int k0 = 0; k0 < 32; k0 += 8) {
            unsigned a[4][4], b[4][2];
            #pragma unroll
            for (int mi = 0; mi < 4; mi++) {
                int mb = warp_m * 64 + mi * 16;
                a[mi][0] = __float_as_uint(Ab[(mb + g    ) * 36 + k0 + tg    ]);
                a[mi][1] = __float_as_uint(Ab[(mb + g + 8) * 36 + k0 + tg    ]);
                a[mi][2] = __float_as_uint(Ab[(mb + g    ) * 36 + k0 + tg + 4]);
                a[mi][3] = __float_as_uint(Ab[(mb + g + 8) * 36 + k0 + tg + 4]);
            }
            #pragma unroll
            for (int ni = 0; ni < 4; ni++) {
                int nb = warp_n * 32 + ni * 8;
                b[ni][0] = __float_as_uint(Wb[(k0 + tg    ) * 136 + nb + g]);
                b[ni][1] = __float_as_uint(Wb[(k0 + tg + 4) * 136 + nb + g]);
            }
            #pragma unroll
            for (int mi = 0; mi < 4; mi++)
                #pragma unroll
                for (int ni = 0; ni < 4; ni++)
                    mma_tf32(acc[mi][ni], a[mi], b[ni]);
        }
        __syncthreads();
    }

    #pragma unroll
    for (int mi = 0; mi < 4; mi++) {
        int r = r0 + warp_m * 64 + mi * 16 + g;
        #pragma unroll
        for (int ni = 0; ni < 4; ni++) {
            int c = c0 + warp_n * 32 + ni * 8 + tg * 2;
            *(__nv_bfloat162*)&C[(size_t)r * DIMN + c] =
                __floats2bfloat162_rn(acc[mi][ni][0], acc[mi][ni][1]);
            *(__nv_bfloat162*)&C[(size_t)(r + 8) * DIMN + c] =
                __floats2bfloat162_rn(acc[mi][ni][2], acc[mi][ni][3]);
        }
    }
}

// ---------------- kernel 3: scores -> exp(S/8) bf16 + Z row sums ------------
// grid (32 s-tiles, 16 t-tiles, 8 heads); block 256 (warps 2x4, 64x32 tile).
__global__ void __launch_bounds__(256) scores_exp_kernel()
{
    __shared__ __align__(16) char sQ[128 * 128];
    __shared__ __align__(16) char sK[128 * 128];
    __shared__ float zrow[128];

    const int tid  = threadIdx.x;
    const int lane = tid & 31;
    const int wid  = tid >> 5;
    const int wm   = wid & 1;
    const int wn   = wid >> 1;
    const int g    = lane >> 2;
    const int tg   = lane & 3;
    const int bs   = blockIdx.x;
    const int bt   = blockIdx.y;
    const int h    = blockIdx.z;

    const uint32_t qb = (uint32_t)__cvta_generic_to_shared(sQ);
    const uint32_t kb = (uint32_t)__cvta_generic_to_shared(sK);

    load_tile_ca(g_Qb + (size_t)(bt * 128) * DIMN + h * HDIM, qb, tid);
    load_tile_ca(g_Kb + (size_t)(bs * 128) * DIMN + h * HDIM, kb, tid);
    CP_COMMIT();
    if (tid < 128) zrow[tid] = 0.0f;
    CP_WAIT0();
    __syncthreads();

    float acc[4][4][4];
    #pragma unroll
    for (int i = 0; i < 4; i++)
        #pragma unroll
        for (int j = 0; j < 4; j++)
            #pragma unroll
            for (int q = 0; q < 4; q++) acc[i][j][q] = 0.0f;
    mma_tile(acc, qb, kb, wm, wn, lane);

    float zacc[4][2];
    #pragma unroll
    for (int mi = 0; mi < 4; mi++) { zacc[mi][0] = 0.0f; zacc[mi][1] = 0.0f; }

    #pragma unroll
    for (int mi = 0; mi < 4; mi++) {
        int r = bt * 128 + wm * 64 + mi * 16 + g;
        size_t base0 = ((size_t)h * TGTN + r) * SRCN;
        size_t base1 = base0 + (size_t)8 * SRCN;
        #pragma unroll
        for (int ni = 0; ni < 4; ni++) {
            int c = bs * 128 + wn * 32 + ni * 8 + tg * 2;
            float e0 = __expf(acc[mi][ni][0] * 0.125f);
            float e1 = __expf(acc[mi][ni][1] * 0.125f);
            float e2 = __expf(acc[mi][ni][2] * 0.125f);
            float e3 = __expf(acc[mi][ni][3] * 0.125f);
            *(__nv_bfloat162*)&g_Sb[base0 + c] = __floats2bfloat162_rn(e0, e1);
            *(__nv_bfloat162*)&g_Sb[base1 + c] = __floats2bfloat162_rn(e2, e3);
            zacc[mi][0] += e0 + e1;
            zacc[mi][1] += e2 + e3;
        }
    }

    // reduce row partials: sum over tg (lanes differing in bits 0-1), then smem
    #pragma unroll
    for (int mi = 0; mi < 4; mi++)
        #pragma unroll
        for (int half = 0; half < 2; half++) {
            float v = zacc[mi][half];
            v += __shfl_xor_sync(0xffffffffu, v, 1);
            v += __shfl_xor_sync(0xffffffffu, v, 2);
            if (tg == 0) atomicAdd(&zrow[wm * 64 + mi * 16 + half * 8 + g], v);
        }
    __syncthreads();
    if (tid < 128)
        atomicAdd(&g_Z[h * TGTN + bt * 128 + tid], zrow[tid]);
}

// ---------------- kernel 4: fused attn-combine + scatter + softmax + mix ----
// one block per target row t; smem = bf16 ext table (72KB) -> 2 CTAs/SM.
__global__ void __launch_bounds__(1024, 2) final_kernel(
    const float* __restrict__ logits, const int* __restrict__ ids,
    float* __restrict__ out)
{
    extern __shared__ char smraw[];
    __nv_bfloat162* ext2 = (__nv_bfloat162*)smraw;              // EXTV/2 pairs
    float* red = (float*)(smraw + EXTV * 2);                    // 32
    float* wsh = red + 32;                                      // 8

    const int t    = blockIdx.x;
    const int tid  = threadIdx.x;
    const int lane = tid & 31;
    const int wid  = tid >> 5;

    // zero ext table
    {
        uint4 z4 = make_uint4(0u, 0u, 0u, 0u);
        uint4* e4 = (uint4*)smraw;
        for (int i = tid; i < EXTV * 2 / 16; i += 1024) e4[i] = z4;
    }
    if (tid < NHEAD) wsh[tid] = 0.125f / g_Z[tid * TGTN + t];
    __syncthreads();

    // scatter: combine heads on the fly, bf16x2 atomic into ext table
    const int2* id2 = (const int2*)ids;
    for (int i = tid; i < SRCN / 2; i += 1024) {
        float a0 = 0.0f, a1 = 0.0f;
        #pragma unroll
        for (int h = 0; h < NHEAD; h++) {
            const __nv_bfloat162* sp =
                (const __nv_bfloat162*)(g_Sb + ((size_t)h * TGTN + t) * SRCN);
            float2 v = __bfloat1622float2(sp[i]);
            float wh = wsh[h];
            a0 = fmaf(v.x, wh, a0);
            a1 = fmaf(v.y, wh, a1);
        }
        int2 d = id2[i];
        atomicAdd(&ext2[d.x >> 1],
                  (d.x & 1) ? __floats2bfloat162_rn(0.0f, a0)
                            : __floats2bfloat162_rn(a0, 0.0f));
        atomicAdd(&ext2[d.y >> 1],
                  (d.y & 1) ? __floats2bfloat162_rn(0.0f, a1)
                            : __floats2bfloat162_rn(a1, 0.0f));
    }

    // pass 1: sum of exp over logits (bounded, no max needed)
    const float* lg = logits + (size_t)t * NVOC;
    float ssum = 0.0f;
    for (int i = tid; i < NVOC; i += 1024) ssum += __expf(lg[i]);
    ssum = warp_sum(ssum);
    if (lane == 0) red[wid] = ssum;
    __syncthreads();                 // also fences the scatter atomics
    if (wid == 0) {
        float x = red[lane];
        x = warp_sum(x);
        if (lane == 0) red[0] = x;
    }
    __syncthreads();
    const float lse = __logf(red[0]);

    const float lk    = g_lk[t];
    const float copyp = __expf(g_lc[t]);

    // pass 2: outputs (logits row is L2-hot from pass 1)
    const __nv_bfloat16* ext = (const __nv_bfloat16*)smraw;
    float* op = out + (size_t)t * EXTV;
    for (int v = tid; v < EXTV; v += 1024) {
        float base = (v < NVOC) ? (lg[v] - lse + lk) : -1e9f;
        float e = __bfloat162float(ext[v]);
        op[v] = (e > 0.0f) ? __logf(__expf(base) + e * copyp) : base;
    }
}

// ---------------- host launcher ---------------------------------------------
extern "C" void kernel_launch(void* const* d_in, const int* in_sizes, int n_in,
                              void* d_out, int out_size)
{
    const float* logits = (const float*)d_in[0];
    const int*   ids    = (const int*)d_in[1];
    const float* src    = (const float*)d_in[2];
    const float* tgt    = (const float*)d_in[3];
    const float* w_lin;
    const float* b_lin;
    const float* Wq;
    const float* Wk;
    if (n_in >= 9 && in_sizes[4] == 1) {
        w_lin = (const float*)d_in[5];
        b_lin = (const float*)d_in[6];
        Wq    = (const float*)d_in[7];
        Wk    = (const float*)d_in[8];
    } else {
        w_lin = (const float*)d_in[4];
        b_lin = (const float*)d_in[5];
        Wq    = (const float*)d_in[6];
        Wk    = (const float*)d_in[7];
    }

    static const int FINAL_SMEM = EXTV * 2 + 40 * 4;   // 72,352 B

    static bool            inited = false;
    static __nv_bfloat16*  pQ = nullptr;
    static __nv_bfloat16*  pK = nullptr;
    if (!inited) {
        cudaFuncSetAttribute(final_kernel,
                             cudaFuncAttributeMaxDynamicSharedMemorySize,
                             FINAL_SMEM);
        void* tmp;
        cudaGetSymbolAddress(&tmp, g_Qb); pQ = (__nv_bfloat16*)tmp;
        cudaGetSymbolAddress(&tmp, g_Kb); pK = (__nv_bfloat16*)tmp;
        inited = true;
    }

    float* out = (float*)d_out;

    // 1) gating scalars + Z zeroing (fused)
    z_kernel<<<TGTN / 8, 256>>>(tgt, w_lin, b_lin);

    // 2) both projections in one launch (tf32 mma, cp.async pipeline)
    proj_gemm_fused<<<dim3(DIMN / 128, 48), 256>>>(tgt, src, Wq, Wk, pQ, pK);

    // 3) per-head exp-scores + Z row sums
    scores_exp_kernel<<<dim3(SRCN / 128, TGTN / 128, NHEAD), 256>>>();

    // 4) fused head-combine + scatter + log_softmax + logaddexp
    final_kernel<<<TGTN, 1024, FINAL_SMEM>>>(logits, ids, out);
}

// round 11
// speedup vs baseline: 1.5389x; 1.0242x over previous
#include <cuda_runtime.h>
#include <cuda_bf16.h>
#include <cuda_fp16.h>
#include <math.h>
#include <stdint.h>
#include <cstdint>

#define TGTN 2048
#define SRCN 4096
#define DIMN 512
#define NHEAD 8
#define HDIM 64
#define NVOC 32000
#define EXTV 36096

// ---------------- scratch (device globals; no allocation allowed) ----------
__device__ __nv_bfloat16 g_Qb[TGTN * DIMN];                   // 2 MB (L2-resident)
__device__ __nv_bfloat16 g_Kb[SRCN * DIMN];                   // 4 MB (L2-resident)
__device__ unsigned char g_S8[(size_t)NHEAD * TGTN * SRCN];   // 64 MB exp(S/8), fp8 e4m3
__device__ float         g_Z[NHEAD * TGTN];                   // softmax denominators
__device__ float         g_lk[TGTN];                          // log_keep
__device__ float         g_lc[TGTN];                          // log_copy

// ---------------- helpers ---------------------------------------------------
__device__ __forceinline__ float log_sigmoid_f(float x) {
    return fminf(x, 0.0f) - log1pf(expf(-fabsf(x)));
}
__device__ __forceinline__ float warp_sum(float v) {
    #pragma unroll
    for (int o = 16; o > 0; o >>= 1) v += __shfl_xor_sync(0xffffffffu, v, o);
    return v;
}
__device__ __forceinline__ void cp16(uint32_t sm, const void* g) {
    asm volatile("cp.async.cg.shared.global [%0], [%1], 16;\n" :: "r"(sm), "l"(g));
}
#define CP_COMMIT() asm volatile("cp.async.commit_group;\n" ::: "memory")
#define CP_WAIT0()  asm volatile("cp.async.wait_group 0;\n" ::: "memory")

__device__ __forceinline__ void mma_tf32(float* c, const unsigned* a, const unsigned* b) {
    asm volatile(
        "mma.sync.aligned.m16n8k8.row.col.f32.tf32.tf32.f32 "
        "{%0,%1,%2,%3},{%4,%5,%6,%7},{%8,%9},{%0,%1,%2,%3};\n"
        : "+f"(c[0]), "+f"(c[1]), "+f"(c[2]), "+f"(c[3])
        : "r"(a[0]), "r"(a[1]), "r"(a[2]), "r"(a[3]), "r"(b[0]), "r"(b[1]));
}
__device__ __forceinline__ void mma_bf16(float* c, const unsigned* a, const unsigned* b) {
    asm volatile(
        "mma.sync.aligned.m16n8k16.row.col.f32.bf16.bf16.f32 "
        "{%0,%1,%2,%3},{%4,%5,%6,%7},{%8,%9},{%0,%1,%2,%3};\n"
        : "+f"(c[0]), "+f"(c[1]), "+f"(c[2]), "+f"(c[3])
        : "r"(a[0]), "r"(a[1]), "r"(a[2]), "r"(a[3]), "r"(b[0]), "r"(b[1]));
}
__device__ __forceinline__ void ldsm_x4(unsigned& r0, unsigned& r1, unsigned& r2,
                                        unsigned& r3, uint32_t addr) {
    asm volatile("ldmatrix.sync.aligned.m8n8.x4.shared.b16 {%0,%1,%2,%3}, [%4];\n"
                 : "=r"(r0), "=r"(r1), "=r"(r2), "=r"(r3) : "r"(addr));
}
// pack two f32 -> fp8x2 (e4m3, satfinite); low byte = first arg
__device__ __forceinline__ unsigned short f2e4m3x2(float lo, float hi) {
    unsigned short p;
    asm("cvt.rn.satfinite.e4m3x2.f32 %0, %1, %2;" : "=h"(p) : "f"(hi), "f"(lo));
    return p;
}
// unpack fp8x2 -> float2
__device__ __forceinline__ float2 e4m3x2_2f(unsigned short p) {
    uint32_t h2;
    asm("cvt.rn.f16x2.e4m3x2 %0, %1;" : "=r"(h2) : "h"(p));
    return __half22float2(*(__half2*)&h2);
}

// swizzled 128x64-bf16 tile via cp.async: row pitch 128B, chunk ^= (row&7)
__device__ __forceinline__ void load_tile_ca(const __nv_bfloat16* __restrict__ g,
                                             uint32_t smBase, int tid) {
    #pragma unroll
    for (int it = 0; it < 4; it++) {
        int row = it * 32 + (tid >> 3);
        int c   = tid & 7;
        cp16(smBase + row * 128 + ((c ^ (row & 7)) * 16),
             g + (size_t)row * DIMN + c * 8);
    }
}
__device__ __forceinline__ uint32_t tile_addr(uint32_t base, int row0, int k0, int lane) {
    int r     = row0 + (lane & 15);
    int chunk = (k0 >> 3) + (lane >> 4);
    return base + r * 128 + ((chunk ^ (r & 7)) * 16);
}
// acc[4][4][4] += Q_tile(128x64) @ K_tile(128x64)^T  (warp tile 64x32)
__device__ __forceinline__ void mma_tile(float acc[4][4][4], uint32_t qb, uint32_t kb,
                                         int wm, int wn, int lane) {
    #pragma unroll
    for (int k0 = 0; k0 < HDIM; k0 += 16) {
        unsigned a[4][4], b[4][2];
        #pragma unroll
        for (int mi = 0; mi < 4; mi++)
            ldsm_x4(a[mi][0], a[mi][1], a[mi][2], a[mi][3],
                    tile_addr(qb, wm * 64 + mi * 16, k0, lane));
        #pragma unroll
        for (int nj = 0; nj < 2; nj++) {
            unsigned t0, t1, t2, t3;
            ldsm_x4(t0, t1, t2, t3, tile_addr(kb, wn * 32 + nj * 16, k0, lane));
            b[2 * nj][0]     = t0; b[2 * nj][1]     = t2;
            b[2 * nj + 1][0] = t1; b[2 * nj + 1][1] = t3;
        }
        #pragma unroll
        for (int mi = 0; mi < 4; mi++)
            #pragma unroll
            for (int ni = 0; ni < 4; ni++)
                mma_bf16(acc[mi][ni], a[mi], b[ni]);
    }
}

// ---------------- kernel 1: z / log_copy / log_keep + zero Z ----------------
__global__ void __launch_bounds__(256) z_kernel(
    const float* __restrict__ tgt, const float* __restrict__ w_lin,
    const float* __restrict__ b_lin)
{
    int gidx = blockIdx.x * 256 + threadIdx.x;
    if (gidx < NHEAD * TGTN) g_Z[gidx] = 0.0f;

    int row  = blockIdx.x * 8 + (threadIdx.x >> 5);
    int lane = threadIdx.x & 31;
    if (row >= TGTN) return;
    const float* tp = tgt + (size_t)row * DIMN;
    float s = 0.0f;
    #pragma unroll
    for (int i = 0; i < DIMN / 32; i++) s += tp[lane + i * 32] * w_lin[lane + i * 32];
    s = warp_sum(s);
    if (lane == 0) {
        float z = s + b_lin[0];
        g_lc[row] = log_sigmoid_f(z);
        g_lk[row] = log_sigmoid_f(-z);
    }
}

// ---------------- kernel 2: fused projection GEMMs (tf32 mma, cp.async) -----
__global__ void __launch_bounds__(256, 2) proj_gemm_fused(
    const float* __restrict__ tgt, const float* __restrict__ src,
    const float* __restrict__ Wq,  const float* __restrict__ Wk,
    __nv_bfloat16* __restrict__ pQ, __nv_bfloat16* __restrict__ pK)
{
    __shared__ float As[2][128 * 36];
    __shared__ float Ws[2][32 * 136];

    const bool isK = blockIdx.y >= 16;
    const float* A = isK ? src : tgt;
    const float* W = isK ? Wk  : Wq;
    __nv_bfloat16* C = isK ? pK : pQ;
    const int r0 = (isK ? (blockIdx.y - 16) : blockIdx.y) * 128;
    const int c0 = blockIdx.x * 128;

    const int tid    = threadIdx.x;
    const int lane   = tid & 31;
    const int wid    = tid >> 5;
    const int warp_m = wid & 1;
    const int warp_n = wid >> 1;
    const int g      = lane >> 2;
    const int tg     = lane & 3;

    const uint32_t asB = (uint32_t)__cvta_generic_to_shared(&As[0][0]);
    const uint32_t wsB = (uint32_t)__cvta_generic_to_shared(&Ws[0][0]);
    const uint32_t asPitch = 128 * 36 * 4;
    const uint32_t wsPitch = 32 * 136 * 4;

    const int ar  = tid >> 3, ac4 = tid & 7;
    const int wkr = tid >> 5, wc4 = tid & 31;

    {
        #pragma unroll
        for (int t = 0; t < 4; t++) {
            int r = ar + t * 32;
            cp16(asB + r * 144 + ac4 * 16, &A[(size_t)(r0 + r) * DIMN + ac4 * 4]);
        }
        #pragma unroll
        for (int t = 0; t < 4; t++) {
            int kr = wkr + t * 8;
            cp16(wsB + kr * 544 + wc4 * 16, &W[(size_t)kr * DIMN + c0 + wc4 * 4]);
        }
        CP_COMMIT();
    }

    float acc[4][4][4];
    #pragma unroll
    for (int i = 0; i < 4; i++)
        #pragma unroll
        for (int j = 0; j < 4; j++)
            #pragma unroll
            for (int q = 0; q < 4; q++) acc[i][j][q] = 0.0f;

    #pragma unroll 1
    for (int it = 0; it < DIMN / 32; it++) {
        CP_WAIT0();
        __syncthreads();
        const int cur = it & 1;

        if (it + 1 < DIMN / 32) {
            const int nxt = cur ^ 1;
            const int kc  = (it + 1) * 32;
            #pragma unroll
            for (int t = 0; t < 4; t++) {
                int r = ar + t * 32;
                cp16(asB + nxt * asPitch + r * 144 + ac4 * 16,
                     &A[(size_t)(r0 + r) * DIMN + kc + ac4 * 4]);
            }
            #pragma unroll
            for (int t = 0; t < 4; t++) {
                int kr = wkr + t * 8;
                cp16(wsB + nxt * wsPitch + kr * 544 + wc4 * 16,
                     &W[(size_t)(kc + kr) * DIMN + c0 + wc4 * 4]);
            }
            CP_COMMIT();
        }

        const float* Ab = As[cur];
        const float* Wb = Ws[cur];
        #pragma unroll
        for (int k0 = 0; k0 < 32; k0 += 8) {
            unsigned a[4][4], b[4][2];
            #pragma unroll
            for (int mi = 0; mi < 4; mi++) {
                int mb = warp_m * 64 + mi * 16;
                a[mi][0] = __float_as_uint(Ab[(mb + g    ) * 36 + k0 + tg    ]);
                a[mi][1] = __float_as_uint(Ab[(mb + g + 8) * 36 + k0 + tg    ]);
                a[mi][2] = __float_as_uint(Ab[(mb + g    ) * 36 + k0 + tg + 4]);
                a[mi][3] = __float_as_uint(Ab[(mb + g + 8) * 36 + k0 + tg + 4]);
            }
            #pragma unroll
            for (int ni = 0; ni < 4; ni++) {
                int nb = warp_n * 32 + ni * 8;
                b[ni][0] = __float_as_uint(Wb[(k0 + tg    ) * 136 + nb + g]);
                b[ni][1] = __float_as_uint(Wb[(k0 + tg + 4) * 136 + nb + g]);
            }
            #pragma unroll
            for (int mi = 0; mi < 4; mi++)
                #pragma unroll
                for (int ni = 0; ni < 4; ni++)
                    mma_tf32(acc[mi][ni], a[mi], b[ni]);
        }
        __syncthreads();
    }

    #pragma unroll
    for (int mi = 0; mi < 4; mi++) {
        int r = r0 + warp_m * 64 + mi * 16 + g;
        #pragma unroll
        for (int ni = 0; ni < 4; ni++) {
            int c = c0 + warp_n * 32 + ni * 8 + tg * 2;
            *(__nv_bfloat162*)&C[(size_t)r * DIMN + c] =
                __floats2bfloat162_rn(acc[mi][ni][0], acc[mi][ni][1]);
            *(__nv_bfloat162*)&C[(size_t)(r + 8) * DIMN + c] =
                __floats2bfloat162_rn(acc[mi][ni][2], acc[mi][ni][3]);
        }
    }
}

// ---------------- kernel 3: scores -> exp(S/8) fp8 + Z row sums -------------
// grid (32 s-tiles, 16 t-tiles, 8 heads); block 256 (warps 2x4, 64x32 tile).
__global__ void __launch_bounds__(256) scores_exp_kernel()
{
    __shared__ __align__(16) char sQ[128 * 128];
    __shared__ __align__(16) char sK[128 * 128];
    __shared__ float zrow[128];

    const int tid  = threadIdx.x;
    const int lane = tid & 31;
    const int wid  = tid >> 5;
    const int wm   = wid & 1;
    const int wn   = wid >> 1;
    const int g    = lane >> 2;
    const int tg   = lane & 3;
    const int bs   = blockIdx.x;
    const int bt   = blockIdx.y;
    const int h    = blockIdx.z;

    const uint32_t qb = (uint32_t)__cvta_generic_to_shared(sQ);
    const uint32_t kb = (uint32_t)__cvta_generic_to_shared(sK);

    load_tile_ca(g_Qb + (size_t)(bt * 128) * DIMN + h * HDIM, qb, tid);
    load_tile_ca(g_Kb + (size_t)(bs * 128) * DIMN + h * HDIM, kb, tid);
    CP_COMMIT();
    if (tid < 128) zrow[tid] = 0.0f;
    CP_WAIT0();
    __syncthreads();

    float acc[4][4][4];
    #pragma unroll
    for (int i = 0; i < 4; i++)
        #pragma unroll
        for (int j = 0; j < 4; j++)
            #pragma unroll
            for (int q = 0; q < 4; q++) acc[i][j][q] = 0.0f;
    mma_tile(acc, qb, kb, wm, wn, lane);

    float zacc[4][2];
    #pragma unroll
    for (int mi = 0; mi < 4; mi++) { zacc[mi][0] = 0.0f; zacc[mi][1] = 0.0f; }

    #pragma unroll
    for (int mi = 0; mi < 4; mi++) {
        int r = bt * 128 + wm * 64 + mi * 16 + g;
        size_t base0 = ((size_t)h * TGTN + r) * SRCN;
        size_t base1 = base0 + (size_t)8 * SRCN;
        #pragma unroll
        for (int ni = 0; ni < 4; ni++) {
            int c = bs * 128 + wn * 32 + ni * 8 + tg * 2;
            float e0 = __expf(acc[mi][ni][0] * 0.125f);
            float e1 = __expf(acc[mi][ni][1] * 0.125f);
            float e2 = __expf(acc[mi][ni][2] * 0.125f);
            float e3 = __expf(acc[mi][ni][3] * 0.125f);
            *(unsigned short*)&g_S8[base0 + c] = f2e4m3x2(e0, e1);
            *(unsigned short*)&g_S8[base1 + c] = f2e4m3x2(e2, e3);
            zacc[mi][0] += e0 + e1;
            zacc[mi][1] += e2 + e3;
        }
    }

    #pragma unroll
    for (int mi = 0; mi < 4; mi++)
        #pragma unroll
        for (int half = 0; half < 2; half++) {
            float v = zacc[mi][half];
            v += __shfl_xor_sync(0xffffffffu, v, 1);
            v += __shfl_xor_sync(0xffffffffu, v, 2);
            if (tg == 0) atomicAdd(&zrow[wm * 64 + mi * 16 + half * 8 + g], v);
        }
    __syncthreads();
    if (tid < 128)
        atomicAdd(&g_Z[h * TGTN + bt * 128 + tid], zrow[tid]);
}

// ---------------- kernel 4: fused attn-combine + scatter + softmax + mix ----
// one block per target row t; smem = bf16 ext table (72KB) -> 2 CTAs/SM.
// all streaming loops vectorized x4.
__global__ void __launch_bounds__(1024, 2) final_kernel(
    const float* __restrict__ logits, const int* __restrict__ ids,
    float* __restrict__ out)
{
    extern __shared__ char smraw[];
    __nv_bfloat162* ext2 = (__nv_bfloat162*)smraw;              // EXTV/2 pairs
    float* red = (float*)(smraw + EXTV * 2);                    // 32
    float* wsh = red + 32;                                      // 8

    const int t    = blockIdx.x;
    const int tid  = threadIdx.x;
    const int lane = tid & 31;
    const int wid  = tid >> 5;

    // zero ext table (72192 B = 4512 uint4)
    {
        uint4 z4 = make_uint4(0u, 0u, 0u, 0u);
        uint4* e4 = (uint4*)smraw;
        for (int i = tid; i < EXTV * 2 / 16; i += 1024) e4[i] = z4;
    }
    if (tid < NHEAD) wsh[tid] = 0.125f / g_Z[tid * TGTN + t];
    __syncthreads();

    // scatter: SRCN/4 = 1024 -> exactly one 4-wide iteration per thread
    {
        const int i = tid;
        float a0 = 0.0f, a1 = 0.0f, a2 = 0.0f, a3 = 0.0f;
        #pragma unroll
        for (int h = 0; h < NHEAD; h++) {
            const uint32_t* sp =
                (const uint32_t*)(g_S8 + ((size_t)h * TGTN + t) * SRCN);
            uint32_t p = sp[i];
            float2 f01 = e4m3x2_2f((unsigned short)(p & 0xffffu));
            float2 f23 = e4m3x2_2f((unsigned short)(p >> 16));
            float wh = wsh[h];
            a0 = fmaf(f01.x, wh, a0);
            a1 = fmaf(f01.y, wh, a1);
            a2 = fmaf(f23.x, wh, a2);
            a3 = fmaf(f23.y, wh, a3);
        }
        int4 d = ((const int4*)ids)[i];
        atomicAdd(&ext2[d.x >> 1], (d.x & 1) ? __floats2bfloat162_rn(0.0f, a0)
                                             : __floats2bfloat162_rn(a0, 0.0f));
        atomicAdd(&ext2[d.y >> 1], (d.y & 1) ? __floats2bfloat162_rn(0.0f, a1)
                                             : __floats2bfloat162_rn(a1, 0.0f));
        atomicAdd(&ext2[d.z >> 1], (d.z & 1) ? __floats2bfloat162_rn(0.0f, a2)
                                             : __floats2bfloat162_rn(a2, 0.0f));
        atomicAdd(&ext2[d.w >> 1], (d.w & 1) ? __floats2bfloat162_rn(0.0f, a3)
                                             : __floats2bfloat162_rn(a3, 0.0f));
    }

    // pass 1: sum of exp over logits (bounded; no max pass), float4 loads
    const float4* lg4 = (const float4*)(logits + (size_t)t * NVOC);
    float ssum = 0.0f;
    for (int i = tid; i < NVOC / 4; i += 1024) {
        float4 x = lg4[i];
        ssum += __expf(x.x) + __expf(x.y) + __expf(x.z) + __expf(x.w);
    }
    ssum = warp_sum(ssum);
    if (lane == 0) red[wid] = ssum;
    __syncthreads();                 // also fences the scatter atomics
    if (wid == 0) {
        float x = red[lane];
        x = warp_sum(x);
        if (lane == 0) red[0] = x;
    }
    __syncthreads();
    const float lse = __logf(red[0]);

    const float lk    = g_lk[t];
    const float copyp = __expf(g_lc[t]);

    // pass 2: outputs, float4 stores (logits row L2-hot from pass 1)
    const uint2* extv = (const uint2*)smraw;     // 4 bf16 per uint2
    float4* op4 = (float4*)(out + (size_t)t * EXTV);
    for (int i = tid; i < EXTV / 4; i += 1024) {
        uint2 ee = extv[i];
        float2 f01 = __bfloat1622float2(*(__nv_bfloat162*)&ee.x);
        float2 f23 = __bfloat1622float2(*(__nv_bfloat162*)&ee.y);
        float4 o;
        if (i < NVOC / 4) {
            float4 x = lg4[i];
            float b0 = x.x - lse + lk, b1 = x.y - lse + lk;
            float b2 = x.z - lse + lk, b3 = x.w - lse + lk;
            o.x = (f01.x > 0.0f) ? __logf(__expf(b0) + f01.x * copyp) : b0;
            o.y = (f01.y > 0.0f) ? __logf(__expf(b1) + f01.y * copyp) : b1;
            o.z = (f23.x > 0.0f) ? __logf(__expf(b2) + f23.x * copyp) : b2;
            o.w = (f23.y > 0.0f) ? __logf(__expf(b3) + f23.y * copyp) : b3;
        } else {
            o.x = (f01.x > 0.0f) ? __logf(f01.x * copyp) : -1e9f;
            o.y = (f01.y > 0.0f) ? __logf(f01.y * copyp) : -1e9f;
            o.z = (f23.x > 0.0f) ? __logf(f23.x * copyp) : -1e9f;
            o.w = (f23.y > 0.0f) ? __logf(f23.y * copyp) : -1e9f;
        }
        op4[i] = o;
    }
}

// ---------------- host launcher ---------------------------------------------
extern "C" void kernel_launch(void* const* d_in, const int* in_sizes, int n_in,
                              void* d_out, int out_size)
{
    const float* logits = (const float*)d_in[0];
    const int*   ids    = (const int*)d_in[1];
    const float* src    = (const float*)d_in[2];
    const float* tgt    = (const float*)d_in[3];
    const float* w_lin;
    const float* b_lin;
    const float* Wq;
    const float* Wk;
    if (n_in >= 9 && in_sizes[4] == 1) {
        w_lin = (const float*)d_in[5];
        b_lin = (const float*)d_in[6];
        Wq    = (const float*)d_in[7];
        Wk    = (const float*)d_in[8];
    } else {
        w_lin = (const float*)d_in[4];
        b_lin = (const float*)d_in[5];
        Wq    = (const float*)d_in[6];
        Wk    = (const float*)d_in[7];
    }

    static const int FINAL_SMEM = EXTV * 2 + 40 * 4;   // 72,352 B

    static bool            inited = false;
    static __nv_bfloat16*  pQ = nullptr;
    static __nv_bfloat16*  pK = nullptr;
    if (!inited) {
        cudaFuncSetAttribute(final_kernel,
                             cudaFuncAttributeMaxDynamicSharedMemorySize,
                             FINAL_SMEM);
        void* tmp;
        cudaGetSymbolAddress(&tmp, g_Qb); pQ = (__nv_bfloat16*)tmp;
        cudaGetSymbolAddress(&tmp, g_Kb); pK = (__nv_bfloat16*)tmp;
        inited = true;
    }

    float* out = (float*)d_out;

    // 1) gating scalars + Z zeroing (fused)
    z_kernel<<<TGTN / 8, 256>>>(tgt, w_lin, b_lin);

    // 2) both projections in one launch (tf32 mma, cp.async pipeline)
    proj_gemm_fused<<<dim3(DIMN / 128, 48), 256>>>(tgt, src, Wq, Wk, pQ, pK);

    // 3) per-head exp-scores (fp8 store) + Z row sums
    scores_exp_kernel<<<dim3(SRCN / 128, TGTN / 128, NHEAD), 256>>>();

    // 4) fused head-combine + scatter + log_softmax + logaddexp (x4 vectorized)
    final_kernel<<<TGTN, 1024, FINAL_SMEM>>>(logits, ids, out);
}

// round 12
// speedup vs baseline: 1.5536x; 1.0095x over previous
#include <cuda_runtime.h>
#include <cuda_bf16.h>
#include <cuda_fp16.h>
#include <math.h>
#include <stdint.h>
#include <cstdint>

#define TGTN 2048
#define SRCN 4096
#define DIMN 512
#define NHEAD 8
#define HDIM 64
#define NVOC 32000
#define EXTV 36096

// ---------------- scratch (device globals; no allocation allowed) ----------
__device__ __nv_bfloat16 g_Qb[TGTN * DIMN];                   // 2 MB (L2-resident)
__device__ __nv_bfloat16 g_Kb[SRCN * DIMN];                   // 4 MB (L2-resident)
__device__ unsigned char g_S8[(size_t)NHEAD * TGTN * SRCN];   // 64 MB exp(S/8), fp8 e4m3
__device__ float         g_Z[NHEAD * TGTN];                   // softmax denominators
__device__ float         g_lk[TGTN];                          // log_keep
__device__ float         g_lc[TGTN];                          // log_copy

// ---------------- helpers ---------------------------------------------------
__device__ __forceinline__ float log_sigmoid_f(float x) {
    return fminf(x, 0.0f) - log1pf(expf(-fabsf(x)));
}
__device__ __forceinline__ float warp_sum(float v) {
    #pragma unroll
    for (int o = 16; o > 0; o >>= 1) v += __shfl_xor_sync(0xffffffffu, v, o);
    return v;
}
__device__ __forceinline__ void cp16(uint32_t sm, const void* g) {
    asm volatile("cp.async.cg.shared.global [%0], [%1], 16;\n" :: "r"(sm), "l"(g));
}
#define CP_COMMIT() asm volatile("cp.async.commit_group;\n" ::: "memory")
#define CP_WAIT0()  asm volatile("cp.async.wait_group 0;\n" ::: "memory")

__device__ __forceinline__ void mma_tf32(float* c, const unsigned* a, const unsigned* b) {
    asm volatile(
        "mma.sync.aligned.m16n8k8.row.col.f32.tf32.tf32.f32 "
        "{%0,%1,%2,%3},{%4,%5,%6,%7},{%8,%9},{%0,%1,%2,%3};\n"
        : "+f"(c[0]), "+f"(c[1]), "+f"(c[2]), "+f"(c[3])
        : "r"(a[0]), "r"(a[1]), "r"(a[2]), "r"(a[3]), "r"(b[0]), "r"(b[1]));
}
__device__ __forceinline__ void mma_bf16(float* c, const unsigned* a, const unsigned* b) {
    asm volatile(
        "mma.sync.aligned.m16n8k16.row.col.f32.bf16.bf16.f32 "
        "{%0,%1,%2,%3},{%4,%5,%6,%7},{%8,%9},{%0,%1,%2,%3};\n"
        : "+f"(c[0]), "+f"(c[1]), "+f"(c[2]), "+f"(c[3])
        : "r"(a[0]), "r"(a[1]), "r"(a[2]), "r"(a[3]), "r"(b[0]), "r"(b[1]));
}
__device__ __forceinline__ void ldsm_x4(unsigned& r0, unsigned& r1, unsigned& r2,
                                        unsigned& r3, uint32_t addr) {
    asm volatile("ldmatrix.sync.aligned.m8n8.x4.shared.b16 {%0,%1,%2,%3}, [%4];\n"
                 : "=r"(r0), "=r"(r1), "=r"(r2), "=r"(r3) : "r"(addr));
}
// pack two f32 -> fp8x2 (e4m3, satfinite); low byte = first arg
__device__ __forceinline__ unsigned short f2e4m3x2(float lo, float hi) {
    unsigned short p;
    asm("cvt.rn.satfinite.e4m3x2.f32 %0, %1, %2;" : "=h"(p) : "f"(hi), "f"(lo));
    return p;
}
// unpack fp8x2 -> float2
__device__ __forceinline__ float2 e4m3x2_2f(unsigned short p) {
    uint32_t h2;
    asm("cvt.rn.f16x2.e4m3x2 %0, %1;" : "=r"(h2) : "h"(p));
    return __half22float2(*(__half2*)&h2);
}

// swizzled 128x64-bf16 tile via cp.async: row pitch 128B, chunk ^= (row&7)
__device__ __forceinline__ void load_tile_ca(const __nv_bfloat16* __restrict__ g,
                                             uint32_t smBase, int tid) {
    #pragma unroll
    for (int it = 0; it < 4; it++) {
        int row = it * 32 + (tid >> 3);
        int c   = tid & 7;
        cp16(smBase + row * 128 + ((c ^ (row & 7)) * 16),
             g + (size_t)row * DIMN + c * 8);
    }
}
__device__ __forceinline__ uint32_t tile_addr(uint32_t base, int row0, int k0, int lane) {
    int r     = row0 + (lane & 15);
    int chunk = (k0 >> 3) + (lane >> 4);
    return base + r * 128 + ((chunk ^ (r & 7)) * 16);
}
// acc[4][4][4] += Q_tile(128x64) @ K_tile(128x64)^T  (warp tile 64x32)
__device__ __forceinline__ void mma_tile(float acc[4][4][4], uint32_t qb, uint32_t kb,
                                         int wm, int wn, int lane) {
    #pragma unroll
    for (int k0 = 0; k0 < HDIM; k0 += 16) {
        unsigned a[4][4], b[4][2];
        #pragma unroll
        for (int mi = 0; mi < 4; mi++)
            ldsm_x4(a[mi][0], a[mi][1], a[mi][2], a[mi][3],
                    tile_addr(qb, wm * 64 + mi * 16, k0, lane));
        #pragma unroll
        for (int nj = 0; nj < 2; nj++) {
            unsigned t0, t1, t2, t3;
            ldsm_x4(t0, t1, t2, t3, tile_addr(kb, wn * 32 + nj * 16, k0, lane));
            b[2 * nj][0]     = t0; b[2 * nj][1]     = t2;
            b[2 * nj + 1][0] = t1; b[2 * nj + 1][1] = t3;
        }
        #pragma unroll
        for (int mi = 0; mi < 4; mi++)
            #pragma unroll
            for (int ni = 0; ni < 4; ni++)
                mma_bf16(acc[mi][ni], a[mi], b[ni]);
    }
}

// ---------------- kernel 1: z / log_copy / log_keep + zero Z ----------------
__global__ void __launch_bounds__(256) z_kernel(
    const float* __restrict__ tgt, const float* __restrict__ w_lin,
    const float* __restrict__ b_lin)
{
    int gidx = blockIdx.x * 256 + threadIdx.x;
    if (gidx < NHEAD * TGTN) g_Z[gidx] = 0.0f;

    int row  = blockIdx.x * 8 + (threadIdx.x >> 5);
    int lane = threadIdx.x & 31;
    if (row >= TGTN) return;
    const float* tp = tgt + (size_t)row * DIMN;
    float s = 0.0f;
    #pragma unroll
    for (int i = 0; i < DIMN / 32; i++) s += tp[lane + i * 32] * w_lin[lane + i * 32];
    s = warp_sum(s);
    if (lane == 0) {
        float z = s + b_lin[0];
        g_lc[row] = log_sigmoid_f(z);
        g_lk[row] = log_sigmoid_f(-z);
    }
}

// ---------------- kernel 2: fused projection GEMMs (tf32 mma, cp.async) -----
__global__ void __launch_bounds__(256, 2) proj_gemm_fused(
    const float* __restrict__ tgt, const float* __restrict__ src,
    const float* __restrict__ Wq,  const float* __restrict__ Wk,
    __nv_bfloat16* __restrict__ pQ, __nv_bfloat16* __restrict__ pK)
{
    __shared__ float As[2][128 * 36];
    __shared__ float Ws[2][32 * 136];

    const bool isK = blockIdx.y >= 16;
    const float* A = isK ? src : tgt;
    const float* W = isK ? Wk  : Wq;
    __nv_bfloat16* C = isK ? pK : pQ;
    const int r0 = (isK ? (blockIdx.y - 16) : blockIdx.y) * 128;
    const int c0 = blockIdx.x * 128;

    const int tid    = threadIdx.x;
    const int lane   = tid & 31;
    const int wid    = tid >> 5;
    const int warp_m = wid & 1;
    const int warp_n = wid >> 1;
    const int g      = lane >> 2;
    const int tg     = lane & 3;

    const uint32_t asB = (uint32_t)__cvta_generic_to_shared(&As[0][0]);
    const uint32_t wsB = (uint32_t)__cvta_generic_to_shared(&Ws[0][0]);
    const uint32_t asPitch = 128 * 36 * 4;
    const uint32_t wsPitch = 32 * 136 * 4;

    const int ar  = tid >> 3, ac4 = tid & 7;
    const int wkr = tid >> 5, wc4 = tid & 31;

    {
        #pragma unroll
        for (int t = 0; t < 4; t++) {
            int r = ar + t * 32;
            cp16(asB + r * 144 + ac4 * 16, &A[(size_t)(r0 + r) * DIMN + ac4 * 4]);
        }
        #pragma unroll
        for (int t = 0; t < 4; t++) {
            int kr = wkr + t * 8;
            cp16(wsB + kr * 544 + wc4 * 16, &W[(size_t)kr * DIMN + c0 + wc4 * 4]);
        }
        CP_COMMIT();
    }

    float acc[4][4][4];
    #pragma unroll
    for (int i = 0; i < 4; i++)
        #pragma unroll
        for (int j = 0; j < 4; j++)
            #pragma unroll
            for (int q = 0; q < 4; q++) acc[i][j][q] = 0.0f;

    #pragma unroll 1
    for (int it = 0; it < DIMN / 32; it++) {
        CP_WAIT0();
        __syncthreads();
        const int cur = it & 1;

        if (it + 1 < DIMN / 32) {
            const int nxt = cur ^ 1;
            const int kc  = (it + 1) * 32;
            #pragma unroll
            for (int t = 0; t < 4; t++) {
                int r = ar + t * 32;
                cp16(asB + nxt * asPitch + r * 144 + ac4 * 16,
                     &A[(size_t)(r0 + r) * DIMN + kc + ac4 * 4]);
            }
            #pragma unroll
            for (int t = 0; t < 4; t++) {
                int kr = wkr + t * 8;
                cp16(wsB + nxt * wsPitch + kr * 544 + wc4 * 16,
                     &W[(size_t)(kc + kr) * DIMN + c0 + wc4 * 4]);
            }
            CP_COMMIT();
        }

        const float* Ab = As[cur];
        const float* Wb = Ws[cur];
        #pragma unroll
        for (int k0 = 0; k0 < 32; k0 += 8) {
            unsigned a[4][4], b[4][2];
            #pragma unroll
            for (int mi = 0; mi < 4; mi++) {
                int mb = warp_m * 64 + mi * 16;
                a[mi][0] = __float_as_uint(Ab[(mb + g    ) * 36 + k0 + tg    ]);
                a[mi][1] = __float_as_uint(Ab[(mb + g + 8) * 36 + k0 + tg    ]);
                a[mi][2] = __float_as_uint(Ab[(mb + g    ) * 36 + k0 + tg + 4]);
                a[mi][3] = __float_as_uint(Ab[(mb + g + 8) * 36 + k0 + tg + 4]);
            }
            #pragma unroll
            for (int ni = 0; ni < 4; ni++) {
                int nb = warp_n * 32 + ni * 8;
                b[ni][0] = __float_as_uint(Wb[(k0 + tg    ) * 136 + nb + g]);
                b[ni][1] = __float_as_uint(Wb[(k0 + tg + 4) * 136 + nb + g]);
            }
            #pragma unroll
            for (int mi = 0; mi < 4; mi++)
                #pragma unroll
                for (int ni = 0; ni < 4; ni++)
                    mma_tf32(acc[mi][ni], a[mi], b[ni]);
        }
        __syncthreads();
    }

    #pragma unroll
    for (int mi = 0; mi < 4; mi++) {
        int r = r0 + warp_m * 64 + mi * 16 + g;
        #pragma unroll
        for (int ni = 0; ni < 4; ni++) {
            int c = c0 + warp_n * 32 + ni * 8 + tg * 2;
            *(__nv_bfloat162*)&C[(size_t)r * DIMN + c] =
                __floats2bfloat162_rn(acc[mi][ni][0], acc[mi][ni][1]);
            *(__nv_bfloat162*)&C[(size_t)(r + 8) * DIMN + c] =
                __floats2bfloat162_rn(acc[mi][ni][2], acc[mi][ni][3]);
        }
    }
}

// ---------------- kernel 3: scores -> exp(S/8) fp8 + Z row sums -------------
// S8 stores use DEFAULT policy: the 64 MB must survive in L2 for final_kernel.
__global__ void __launch_bounds__(256) scores_exp_kernel()
{
    __shared__ __align__(16) char sQ[128 * 128];
    __shared__ __align__(16) char sK[128 * 128];
    __shared__ float zrow[128];

    const int tid  = threadIdx.x;
    const int lane = tid & 31;
    const int wid  = tid >> 5;
    const int wm   = wid & 1;
    const int wn   = wid >> 1;
    const int g    = lane >> 2;
    const int tg   = lane & 3;
    const int bs   = blockIdx.x;
    const int bt   = blockIdx.y;
    const int h    = blockIdx.z;

    const uint32_t qb = (uint32_t)__cvta_generic_to_shared(sQ);
    const uint32_t kb = (uint32_t)__cvta_generic_to_shared(sK);

    load_tile_ca(g_Qb + (size_t)(bt * 128) * DIMN + h * HDIM, qb, tid);
    load_tile_ca(g_Kb + (size_t)(bs * 128) * DIMN + h * HDIM, kb, tid);
    CP_COMMIT();
    if (tid < 128) zrow[tid] = 0.0f;
    CP_WAIT0();
    __syncthreads();

    float acc[4][4][4];
    #pragma unroll
    for (int i = 0; i < 4; i++)
        #pragma unroll
        for (int j = 0; j < 4; j++)
            #pragma unroll
            for (int q = 0; q < 4; q++) acc[i][j][q] = 0.0f;
    mma_tile(acc, qb, kb, wm, wn, lane);

    float zacc[4][2];
    #pragma unroll
    for (int mi = 0; mi < 4; mi++) { zacc[mi][0] = 0.0f; zacc[mi][1] = 0.0f; }

    #pragma unroll
    for (int mi = 0; mi < 4; mi++) {
        int r = bt * 128 + wm * 64 + mi * 16 + g;
        size_t base0 = ((size_t)h * TGTN + r) * SRCN;
        size_t base1 = base0 + (size_t)8 * SRCN;
        #pragma unroll
        for (int ni = 0; ni < 4; ni++) {
            int c = bs * 128 + wn * 32 + ni * 8 + tg * 2;
            float e0 = __expf(acc[mi][ni][0] * 0.125f);
            float e1 = __expf(acc[mi][ni][1] * 0.125f);
            float e2 = __expf(acc[mi][ni][2] * 0.125f);
            float e3 = __expf(acc[mi][ni][3] * 0.125f);
            *(unsigned short*)&g_S8[base0 + c] = f2e4m3x2(e0, e1);
            *(unsigned short*)&g_S8[base1 + c] = f2e4m3x2(e2, e3);
            zacc[mi][0] += e0 + e1;
            zacc[mi][1] += e2 + e3;
        }
    }

    #pragma unroll
    for (int mi = 0; mi < 4; mi++)
        #pragma unroll
        for (int half = 0; half < 2; half++) {
            float v = zacc[mi][half];
            v += __shfl_xor_sync(0xffffffffu, v, 1);
            v += __shfl_xor_sync(0xffffffffu, v, 2);
            if (tg == 0) atomicAdd(&zrow[wm * 64 + mi * 16 + half * 8 + g], v);
        }
    __syncthreads();
    if (tid < 128)
        atomicAdd(&g_Z[h * TGTN + bt * 128 + tid], zrow[tid]);
}

// ---------------- kernel 4: fused attn-combine + scatter + softmax + mix ----
// cache policy: S8 loads .cs (one-time), pass-1 logits default (reused in
// pass 2), pass-2 logits .cs (last use), out stores .cs (never re-read).
__global__ void __launch_bounds__(1024, 2) final_kernel(
    const float* __restrict__ logits, const int* __restrict__ ids,
    float* __restrict__ out)
{
    extern __shared__ char smraw[];
    __nv_bfloat162* ext2 = (__nv_bfloat162*)smraw;              // EXTV/2 pairs
    float* red = (float*)(smraw + EXTV * 2);                    // 32
    float* wsh = red + 32;                                      // 8

    const int t    = blockIdx.x;
    const int tid  = threadIdx.x;
    const int lane = tid & 31;
    const int wid  = tid >> 5;

    // zero ext table (72192 B = 4512 uint4)
    {
        uint4 z4 = make_uint4(0u, 0u, 0u, 0u);
        uint4* e4 = (uint4*)smraw;
        for (int i = tid; i < EXTV * 2 / 16; i += 1024) e4[i] = z4;
    }
    if (tid < NHEAD) wsh[tid] = 0.125f / g_Z[tid * TGTN + t];
    __syncthreads();

    // scatter: SRCN/4 = 1024 -> exactly one 4-wide iteration per thread
    {
        const int i = tid;
        float a0 = 0.0f, a1 = 0.0f, a2 = 0.0f, a3 = 0.0f;
        #pragma unroll
        for (int h = 0; h < NHEAD; h++) {
            const unsigned int* sp =
                (const unsigned int*)(g_S8 + ((size_t)h * TGTN + t) * SRCN);
            unsigned int p = __ldcs(sp + i);          // one-time read: evict-first
            float2 f01 = e4m3x2_2f((unsigned short)(p & 0xffffu));
            float2 f23 = e4m3x2_2f((unsigned short)(p >> 16));
            float wh = wsh[h];
            a0 = fmaf(f01.x, wh, a0);
            a1 = fmaf(f01.y, wh, a1);
            a2 = fmaf(f23.x, wh, a2);
            a3 = fmaf(f23.y, wh, a3);
        }
        int4 d = ((const int4*)ids)[i];
        atomicAdd(&ext2[d.x >> 1], (d.x & 1) ? __floats2bfloat162_rn(0.0f, a0)
                                             : __floats2bfloat162_rn(a0, 0.0f));
        atomicAdd(&ext2[d.y >> 1], (d.y & 1) ? __floats2bfloat162_rn(0.0f, a1)
                                             : __floats2bfloat162_rn(a1, 0.0f));
        atomicAdd(&ext2[d.z >> 1], (d.z & 1) ? __floats2bfloat162_rn(0.0f, a2)
                                             : __floats2bfloat162_rn(a2, 0.0f));
        atomicAdd(&ext2[d.w >> 1], (d.w & 1) ? __floats2bfloat162_rn(0.0f, a3)
                                             : __floats2bfloat162_rn(a3, 0.0f));
    }

    // pass 1: sum of exp over logits (bounded; no max pass), float4 loads
    const float4* lg4 = (const float4*)(logits + (size_t)t * NVOC);
    float ssum = 0.0f;
    for (int i = tid; i < NVOC / 4; i += 1024) {
        float4 x = lg4[i];
        ssum += __expf(x.x) + __expf(x.y) + __expf(x.z) + __expf(x.w);
    }
    ssum = warp_sum(ssum);
    if (lane == 0) red[wid] = ssum;
    __syncthreads();                 // also fences the scatter atomics
    if (wid == 0) {
        float x = red[lane];
        x = warp_sum(x);
        if (lane == 0) red[0] = x;
    }
    __syncthreads();
    const float lse = __logf(red[0]);

    const float lk    = g_lk[t];
    const float copyp = __expf(g_lc[t]);

    // pass 2: outputs; logits .cs (last use), out .cs (write-once streaming)
    const uint2* extv = (const uint2*)smraw;     // 4 bf16 per uint2
    float4* op4 = (float4*)(out + (size_t)t * EXTV);
    for (int i = tid; i < EXTV / 4; i += 1024) {
        uint2 ee = extv[i];
        float2 f01 = __bfloat1622float2(*(__nv_bfloat162*)&ee.x);
        float2 f23 = __bfloat1622float2(*(__nv_bfloat162*)&ee.y);
        float4 o;
        if (i < NVOC / 4) {
            float4 x = __ldcs(lg4 + i);
            float b0 = x.x - lse + lk, b1 = x.y - lse + lk;
            float b2 = x.z - lse + lk, b3 = x.w - lse + lk;
            o.x = (f01.x > 0.0f) ? __logf(__expf(b0) + f01.x * copyp) : b0;
            o.y = (f01.y > 0.0f) ? __logf(__expf(b1) + f01.y * copyp) : b1;
            o.z = (f23.x > 0.0f) ? __logf(__expf(b2) + f23.x * copyp) : b2;
            o.w = (f23.y > 0.0f) ? __logf(__expf(b3) + f23.y * copyp) : b3;
        } else {
            o.x = (f01.x > 0.0f) ? __logf(f01.x * copyp) : -1e9f;
            o.y = (f01.y > 0.0f) ? __logf(f01.y * copyp) : -1e9f;
            o.z = (f23.x > 0.0f) ? __logf(f23.x * copyp) : -1e9f;
            o.w = (f23.y > 0.0f) ? __logf(f23.y * copyp) : -1e9f;
        }
        __stcs(op4 + i, o);
    }
}

// ---------------- host launcher ---------------------------------------------
extern "C" void kernel_launch(void* const* d_in, const int* in_sizes, int n_in,
                              void* d_out, int out_size)
{
    const float* logits = (const float*)d_in[0];
    const int*   ids    = (const int*)d_in[1];
    const float* src    = (const float*)d_in[2];
    const float* tgt    = (const float*)d_in[3];
    const float* w_lin;
    const float* b_lin;
    const float* Wq;
    const float* Wk;
    if (n_in >= 9 && in_sizes[4] == 1) {
        w_lin = (const float*)d_in[5];
        b_lin = (const float*)d_in[6];
        Wq    = (const float*)d_in[7];
        Wk    = (const float*)d_in[8];
    } else {
        w_lin = (const float*)d_in[4];
        b_lin = (const float*)d_in[5];
        Wq    = (const float*)d_in[6];
        Wk    = (const float*)d_in[7];
    }

    static const int FINAL_SMEM = EXTV * 2 + 40 * 4;   // 72,352 B

    static bool            inited = false;
    static __nv_bfloat16*  pQ = nullptr;
    static __nv_bfloat16*  pK = nullptr;
    if (!inited) {
        cudaFuncSetAttribute(final_kernel,
                             cudaFuncAttributeMaxDynamicSharedMemorySize,
                             FINAL_SMEM);
        void* tmp;
        cudaGetSymbolAddress(&tmp, g_Qb); pQ = (__nv_bfloat16*)tmp;
        cudaGetSymbolAddress(&tmp, g_Kb); pK = (__nv_bfloat16*)tmp;
        inited = true;
    }

    float* out = (float*)d_out;

    // 1) gating scalars + Z zeroing (fused)
    z_kernel<<<TGTN / 8, 256>>>(tgt, w_lin, b_lin);

    // 2) both projections in one launch (tf32 mma, cp.async pipeline)
    proj_gemm_fused<<<dim3(DIMN / 128, 48), 256>>>(tgt, src, Wq, Wk, pQ, pK);

    // 3) per-head exp-scores (fp8 store, default policy -> stays in L2)
    scores_exp_kernel<<<dim3(SRCN / 128, TGTN / 128, NHEAD), 256>>>();

    // 4) fused head-combine + scatter + log_softmax + logaddexp
    //    (streaming cache hints: .cs on S8 loads, pass-2 logits, out stores)
    final_kernel<<<TGTN, 1024, FINAL_SMEM>>>(logits, ids, out);
}